// round 1
// baseline (speedup 1.0000x reference)
#include <cuda_runtime.h>
#include <math.h>

#define BATCH 64
#define C 128
#define HW 1024
#define OUTC 640                   // 5*C
#define REG_STRIDE (C*HW)          // 131072 per batch for scratch
#define OUT_BSTRIDE (OUTC*HW)      // 655360 per batch for d_out

__device__ float g_s0[BATCH*C*HW];
__device__ float g_s1[BATCH*C*HW];
__device__ float g_wcomb[8*C*C*18];   // [e][ci][tap][co]
__device__ float g_asoft[8*5];

// ---------------------------------------------------------------------------
// softmax over alphas (8 edges x 5 ops)
// ---------------------------------------------------------------------------
__global__ void k_softmax(const float* __restrict__ alphas) {
    int e = threadIdx.x;
    if (e < 8) {
        float m = -1e30f;
        #pragma unroll
        for (int i = 0; i < 5; i++) m = fmaxf(m, alphas[e*5+i]);
        float ex[5]; float s = 0.f;
        #pragma unroll
        for (int i = 0; i < 5; i++) { ex[i] = expf(alphas[e*5+i] - m); s += ex[i]; }
        float inv = 1.f / s;
        #pragma unroll
        for (int i = 0; i < 5; i++) g_asoft[e*5+i] = ex[i] * inv;
    }
}

// ---------------------------------------------------------------------------
// fold a1*w3 (dilation 1) and a2*wd3 (dilation 2) into 18-tap combined weights
// layout: g_wcomb[((e*C + ci)*18 + t)*C + co]
// ---------------------------------------------------------------------------
__global__ void k_combine(const float* __restrict__ w3, const float* __restrict__ wd3) {
    int idx = blockIdx.x * 256 + threadIdx.x;     // e*16384 + ci*128 + co
    if (idx >= 8*C*C) return;
    int e  = idx >> 14;
    int r  = idx & 16383;
    int ci = r >> 7;
    int co = r & 127;
    float a1 = g_asoft[e*5+1], a2 = g_asoft[e*5+2];
    int wb = ((e*C + co)*C + ci)*9;               // source [e][co][ci][3][3]
    int ob = ((e*C + ci)*18)*C + co;
    #pragma unroll
    for (int k = 0; k < 9; k++) g_wcomb[ob + k*C]     = a1 * w3[wb + k];
    #pragma unroll
    for (int k = 0; k < 9; k++) g_wcomb[ob + (9+k)*C] = a2 * wd3[wb + k];
}

// ---------------------------------------------------------------------------
// 1x1 pre-conv: out[b,co,px] = sum_ci in[b,ci,px] * w[co,ci]
// block = (b, 16-co chunk), 256 threads, each: 4 px x 16 co
// ---------------------------------------------------------------------------
__global__ __launch_bounds__(256) void k_pre(const float* __restrict__ in,
                                             const float* __restrict__ w,
                                             float* __restrict__ out) {
    __shared__ __align__(16) float tin[8][HW];
    __shared__ float tw[8][16];
    int b   = blockIdx.x >> 3;
    int co0 = (blockIdx.x & 7) << 4;
    int tid = threadIdx.x;
    int px0 = tid * 4;
    const float* inb = in + b*C*HW;
    float acc[16][4] = {};
    for (int cic = 0; cic < C; cic += 8) {
        __syncthreads();
        #pragma unroll
        for (int k = 0; k < 8; k++) {
            int f = tid + k*256;                       // float4 index into 8*1024 tile
            ((float4*)tin)[f] = ((const float4*)(inb + cic*HW))[f];
        }
        if (tid < 128) {
            int ci = tid >> 4, co = tid & 15;
            tw[ci][co] = w[(co0+co)*C + cic + ci];
        }
        __syncthreads();
        #pragma unroll
        for (int ci = 0; ci < 8; ci++) {
            float4 i4 = *(const float4*)&tin[ci][px0];
            float iv[4] = {i4.x, i4.y, i4.z, i4.w};
            #pragma unroll
            for (int co = 0; co < 16; co++) {
                float wv = tw[ci][co];
                #pragma unroll
                for (int j = 0; j < 4; j++) acc[co][j] += wv * iv[j];
            }
        }
    }
    float* ob = out + (b*C + co0)*HW + px0;
    #pragma unroll
    for (int co = 0; co < 16; co++) {
        float4 v = make_float4(acc[co][0], acc[co][1], acc[co][2], acc[co][3]);
        *(float4*)(ob + co*HW) = v;
    }
}

// ---------------------------------------------------------------------------
// fused node kernel:
//   s_new = mixed(h0, edge eA) + mixed(h1, edge eB)
// conv part uses precombined 18-tap weights; identity/avg/max fused at ci==co.
// block = (b, 16-co chunk); thread = row y, 4 consecutive x.
// ---------------------------------------------------------------------------
__global__ __launch_bounds__(256) void k_node(
    const float* __restrict__ h0, int h0_bs,
    const float* __restrict__ h1, int h1_bs,
    float* __restrict__ out,                 // points at [b=0][node_ch0][0]
    int eA, int eB)
{
    __shared__ __align__(16) float tile[4][36*37];   // [ci][(ty)*37+tx], halo 2
    __shared__ __align__(16) float wsh[4][18][16];
    const int tid = threadIdx.x;
    const int b   = blockIdx.x >> 3;
    const int co0 = (blockIdx.x & 7) << 4;
    const int y   = tid >> 3;          // 0..31
    const int x0  = (tid & 7) << 2;    // 0,4,...,28
    float acc[16][4] = {};

    const int DY[18] = {-1,-1,-1, 0,0,0, 1,1,1,  -2,-2,-2, 0,0,0, 2,2,2};
    const int DX[18] = {-1, 0, 1,-1,0,1,-1,0,1,  -2, 0, 2,-2,0,2,-2,0,2};

    for (int s = 0; s < 2; s++) {
        const float* hb = s ? (h1 + (long long)b*h1_bs) : (h0 + (long long)b*h0_bs);
        const int e = s ? eB : eA;
        const float a0  = g_asoft[e*5+0];
        const float a39 = g_asoft[e*5+3] * (1.f/9.f);
        const float a4  = g_asoft[e*5+4];
        for (int cic = 0; cic < C; cic += 4) {
            __syncthreads();
            // load 4 channels of 36x36 tile (zero halo)
            for (int i = tid; i < 4*1296; i += 256) {
                int ci = i / 1296, r = i - ci*1296;
                int ty = r / 36,  tx = r - ty*36;
                int gy = ty - 2,  gx = tx - 2;
                float v = 0.f;
                if ((unsigned)gy < 32u && (unsigned)gx < 32u)
                    v = hb[(cic + ci)*HW + gy*32 + gx];
                tile[ci][ty*37 + tx] = v;
            }
            // load combined weights for this ci-chunk / co-chunk
            for (int i = tid; i < 4*18*16; i += 256) {
                int ci = i / 288, r = i - ci*288;
                int t = r >> 4, co = r & 15;
                wsh[ci][t][co] = g_wcomb[((e*C + cic + ci)*18 + t)*C + co0 + co];
            }
            __syncthreads();
            // conv accumulate: 18 taps x 4 ci
            #pragma unroll 1
            for (int ci = 0; ci < 4; ci++) {
                const float* tc = &tile[ci][(y+2)*37 + (x0+2)];
                #pragma unroll
                for (int t = 0; t < 18; t++) {
                    const float* tp = tc + DY[t]*37 + DX[t];
                    float in4[4] = {tp[0], tp[1], tp[2], tp[3]};
                    const float4* wp = (const float4*)wsh[ci][t];
                    float wv[16];
                    #pragma unroll
                    for (int q = 0; q < 4; q++) {
                        float4 w = wp[q];
                        wv[q*4+0] = w.x; wv[q*4+1] = w.y; wv[q*4+2] = w.z; wv[q*4+3] = w.w;
                    }
                    #pragma unroll
                    for (int co = 0; co < 16; co++)
                        #pragma unroll
                        for (int j = 0; j < 4; j++)
                            acc[co][j] += wv[co] * in4[j];
                }
            }
            // identity + avg3 + max3 for channels where ci == co
            int lo = (cic > co0) ? cic : co0;
            int hi0 = cic + 4, hi1 = co0 + 16;
            int hi = (hi0 < hi1) ? hi0 : hi1;
            for (int cg = lo; cg < hi; cg++) {
                int ci = cg - cic, coI = cg - co0;
                const float* tc = &tile[ci][(y+2)*37 + (x0+2)];
                #pragma unroll
                for (int j = 0; j < 4; j++) {
                    float cv  = tc[j];
                    float sum = 0.f, mx = -INFINITY;
                    #pragma unroll
                    for (int dy = -1; dy <= 1; dy++)
                        #pragma unroll
                        for (int dx = -1; dx <= 1; dx++) {
                            float v = tc[j + dy*37 + dx];
                            sum += v;
                            bool ok = ((unsigned)(y + dy) < 32u) &&
                                      ((unsigned)(x0 + j + dx) < 32u);
                            if (ok) mx = fmaxf(mx, v);
                        }
                    acc[coI][j] += a0*cv + a39*sum + a4*mx;
                }
            }
        }
    }
    // write s_new into d_out concat layout
    float* ob = out + (long long)b*OUT_BSTRIDE + co0*HW + y*32 + x0;
    #pragma unroll
    for (int co = 0; co < 16; co++) {
        float4 v = make_float4(acc[co][0], acc[co][1], acc[co][2], acc[co][3]);
        *(float4*)(ob + co*HW) = v;
    }
}

// ---------------------------------------------------------------------------
// copy skip_input into concat channels [4C,5C) and (optionally) second output
// ---------------------------------------------------------------------------
__global__ void k_copy_skip(const float* __restrict__ skip,
                            float* __restrict__ out,
                            float* __restrict__ out2) {
    int i = blockIdx.x * 256 + threadIdx.x;       // float4 index
    if (i >= (BATCH*C*HW)/4) return;
    float4 v = ((const float4*)skip)[i];
    int pe = i * 4;
    int b  = pe >> 17;                            // / (C*HW)
    int r  = pe & (C*HW - 1);
    *(float4*)(out + (long long)b*OUT_BSTRIDE + 4*C*HW + r) = v;
    if (out2) ((float4*)out2)[i] = v;
}

// ---------------------------------------------------------------------------
extern "C" void kernel_launch(void* const* d_in, const int* in_sizes, int n_in,
                              void* d_out, int out_size) {
    const float* input0 = (const float*)d_in[0];
    const float* input1 = (const float*)d_in[1];
    const float* skip   = (const float*)d_in[2];
    const float* w_pre0 = (const float*)d_in[3];
    const float* w_pre1 = (const float*)d_in[4];
    const float* w3     = (const float*)d_in[5];
    const float* wd3    = (const float*)d_in[6];
    const float* alphas = (const float*)d_in[7];
    float* out = (float*)d_out;

    float *s0, *s1;
    cudaGetSymbolAddress((void**)&s0, g_s0);
    cudaGetSymbolAddress((void**)&s1, g_s1);

    k_softmax<<<1, 8>>>(alphas);
    k_combine<<<(8*C*C + 255)/256, 256>>>(w3, wd3);
    k_pre<<<BATCH*8, 256>>>(input0, w_pre0, s0);
    k_pre<<<BATCH*8, 256>>>(input1, w_pre1, s1);

    // node 0: h0=s0, h1=s1                      -> out region 0
    k_node<<<BATCH*8, 256>>>(s0, REG_STRIDE, s1, REG_STRIDE,
                             out + 0*C*HW, 0, 1);
    // node 1: h0=s1, h1=s2(out r0)              -> out region 1
    k_node<<<BATCH*8, 256>>>(s1, REG_STRIDE, out + 0*C*HW, OUT_BSTRIDE,
                             out + 1*C*HW, 2, 3);
    // node 2: h0=s2, h1=s3                      -> out region 2
    k_node<<<BATCH*8, 256>>>(out + 0*C*HW, OUT_BSTRIDE, out + 1*C*HW, OUT_BSTRIDE,
                             out + 2*C*HW, 4, 5);
    // node 3: h0=s3, h1=s4                      -> out region 3
    k_node<<<BATCH*8, 256>>>(out + 1*C*HW, OUT_BSTRIDE, out + 2*C*HW, OUT_BSTRIDE,
                             out + 3*C*HW, 6, 7);

    long long concat_elems = (long long)BATCH*OUTC*HW;        // 41,943,040
    long long skip_elems   = (long long)BATCH*C*HW;           //  8,388,608
    float* out2 = nullptr;
    if ((long long)out_size >= concat_elems + skip_elems)
        out2 = out + concat_elems;
    k_copy_skip<<<((BATCH*C*HW/4) + 255)/256, 256>>>(skip, out, out2);
}

// round 3
// speedup vs baseline: 2.2712x; 2.2712x over previous
#include <cuda_runtime.h>
#include <math.h>
#include <stdint.h>

#define BATCH 64
#define C 128
#define HW 1024
#define OUTC 640
#define REG_STRIDE (C*HW)
#define OUT_BSTRIDE (OUTC*HW)

#define KEDGE 2304            // 128 ci * 18 taps
#define NTILE_EDGE 72         // 2304 / 32
#define NTILES 144            // 2 edges
#define TILE_FLOATS 4096      // 128 rows * 32 k
#define TILE_BYTES 16384

// idesc for kind::tf32: dtype=F32(bit4), atype=TF32=2(bits7-9), btype=TF32=2(bits10-12),
// N=128 -> (128/8)<<17, M=128 -> (128/16)<<24
#define IDESC_TF32 0x8200910u

// ---------------------------------------------------------------------------
// Arch-conditional feature detection: tcgen05 is only legal when compiling a
// PTX pass whose target carries the 'a' suffix (sm_103a). In any other pass
// (e.g. compute_103 forward-compat PTX) the tcgen05 kernel compiles empty and
// the FFMA fallback kernel carries the work instead.
// ---------------------------------------------------------------------------
#if defined(__CUDA_ARCH_FEAT_SM103_ALL) || defined(__CUDA_ARCH_FEAT_SM100_ALL) || \
    (defined(__CUDA_ARCH_SPECIFIC__) && (__CUDA_ARCH_SPECIFIC__ >= 1000))
#define HAS_TC05 1
#else
#define HAS_TC05 0
#endif

__device__ float g_s0[BATCH*C*HW];
__device__ float g_s1[BATCH*C*HW];
__device__ __align__(16) uint32_t gA[8*NTILE_EDGE*TILE_FLOATS];  // tf32 bits, swizzled A-tiles
__device__ float g_wcomb[8*C*C*18];   // [e][ci][tap][co]  (FFMA fallback weights)
__device__ int   g_kdec[KEDGE];
__device__ float g_asoft[8*5];

// ---------------------------------------------------------------------------
// generic helpers
// ---------------------------------------------------------------------------
__device__ __forceinline__ uint32_t smem_u32(const void* p) {
    uint32_t a;
    asm("{ .reg .u64 t; cvta.to.shared.u64 t, %1; cvt.u32.u64 %0, t; }" : "=r"(a) : "l"(p));
    return a;
}
#define SW128(o) ((o) ^ (((o) >> 3) & 0x70))
__device__ __forceinline__ uint32_t f2tf32(float f) {
    uint32_t r;
    asm("cvt.rna.tf32.f32 %0, %1;" : "=r"(r) : "f"(f));
    return r;
}

#if HAS_TC05
// ---------------------------------------------------------------------------
// tcgen05 PTX helpers (only compiled when the arch-conditional target exists)
// ---------------------------------------------------------------------------
__device__ __forceinline__ uint32_t elect_one() {
    uint32_t p;
    asm volatile("{ .reg .pred p; elect.sync _|p, 0xFFFFFFFF; selp.b32 %0, 1, 0, p; }" : "=r"(p));
    return p;
}
__device__ __forceinline__ uint64_t make_desc(uint32_t addr) {
    // SW128, version=1(Blackwell), SBO=64, LBO=1  (K-major)
    const uint64_t base = (uint64_t(2) << 61) | (uint64_t(1) << 46)
                        | (uint64_t(64) << 32) | (uint64_t(1) << 16);
    return base | ((uint64_t)(addr >> 4) & 0x3FFF);
}
__device__ __forceinline__ void mma_tf32_ss(uint32_t d, uint64_t ad, uint64_t bd,
                                            uint32_t idesc, uint32_t en) {
    asm volatile(
        "{\n\t.reg .pred p;\n\tsetp.ne.u32 p, %5, 0;\n\t"
        "tcgen05.mma.cta_group::1.kind::tf32 [%0], %1, %2, %3, {%4, %4, %4, %4}, p;\n\t}"
        :: "r"(d), "l"(ad), "l"(bd), "r"(idesc), "r"(0u), "r"(en) : "memory");
}
__device__ __forceinline__ void mbar_init(uint32_t a, uint32_t cnt) {
    asm volatile("mbarrier.init.shared.b64 [%0], %1;" :: "r"(a), "r"(cnt) : "memory");
}
__device__ __forceinline__ void mbar_inval(uint32_t a) {
    asm volatile("mbarrier.inval.shared.b64 [%0];" :: "r"(a) : "memory");
}
__device__ __forceinline__ void mbar_wait(uint32_t a, uint32_t parity) {
    asm volatile(
        "{\n\t.reg .pred P;\n"
        "W_%=:\n\t"
        "mbarrier.try_wait.parity.acquire.cta.shared::cta.b64 P, [%0], %1, 0x989680;\n\t"
        "@P bra D_%=;\n\tbra W_%=;\nD_%=:\n\t}"
        :: "r"(a), "r"(parity) : "memory");
}
__device__ __forceinline__ void tmem_commit(uint32_t mbar) {
    asm volatile(
        "tcgen05.commit.cta_group::1.mbarrier::arrive::one.shared::cluster.b64 [%0];"
        :: "r"(mbar) : "memory");
}
#define TC_ALLOC(dst, n)   asm volatile("tcgen05.alloc.cta_group::1.sync.aligned.shared::cta.b32 [%0], %1;" :: "r"(dst), "r"(n) : "memory")
#define TC_DEALLOC(t, n)   asm volatile("tcgen05.dealloc.cta_group::1.sync.aligned.b32 %0, %1;" :: "r"(t), "r"(n))
#define TC_RELINQ()        asm volatile("tcgen05.relinquish_alloc_permit.cta_group::1.sync.aligned;")
#define TC_FENCE_AFTER()   asm volatile("tcgen05.fence::after_thread_sync;" ::: "memory")
#define TC_FENCE_BEFORE()  asm volatile("tcgen05.fence::before_thread_sync;" ::: "memory")
#define TC_WAIT_LD()       asm volatile("tcgen05.wait::ld.sync.aligned;" ::: "memory")
#define FENCE_ASYNC()      asm volatile("fence.proxy.async.shared::cta;" ::: "memory")

#define LD_X32(r, a) \
    asm volatile("tcgen05.ld.sync.aligned.32x32b.x32.b32 " \
        "{%0,%1,%2,%3,%4,%5,%6,%7,%8,%9,%10,%11,%12,%13,%14,%15," \
        "%16,%17,%18,%19,%20,%21,%22,%23,%24,%25,%26,%27,%28,%29,%30,%31}, [%32];" \
        : "=r"((r)[0]),"=r"((r)[1]),"=r"((r)[2]),"=r"((r)[3]), \
          "=r"((r)[4]),"=r"((r)[5]),"=r"((r)[6]),"=r"((r)[7]), \
          "=r"((r)[8]),"=r"((r)[9]),"=r"((r)[10]),"=r"((r)[11]), \
          "=r"((r)[12]),"=r"((r)[13]),"=r"((r)[14]),"=r"((r)[15]), \
          "=r"((r)[16]),"=r"((r)[17]),"=r"((r)[18]),"=r"((r)[19]), \
          "=r"((r)[20]),"=r"((r)[21]),"=r"((r)[22]),"=r"((r)[23]), \
          "=r"((r)[24]),"=r"((r)[25]),"=r"((r)[26]),"=r"((r)[27]), \
          "=r"((r)[28]),"=r"((r)[29]),"=r"((r)[30]),"=r"((r)[31]) \
        : "r"(a))
#endif  // HAS_TC05

// ---------------------------------------------------------------------------
// softmax over alphas (8 edges x 5 ops)
// ---------------------------------------------------------------------------
__global__ void k_softmax(const float* __restrict__ alphas) {
    int e = threadIdx.x;
    if (e < 8) {
        float m = -1e30f;
        #pragma unroll
        for (int i = 0; i < 5; i++) m = fmaxf(m, alphas[e*5+i]);
        float ex[5]; float s = 0.f;
        #pragma unroll
        for (int i = 0; i < 5; i++) { ex[i] = expf(alphas[e*5+i] - m); s += ex[i]; }
        float inv = 1.f / s;
        #pragma unroll
        for (int i = 0; i < 5; i++) g_asoft[e*5+i] = ex[i] * inv;
    }
}

// ---------------------------------------------------------------------------
// k' -> (ci, dy, dx) decode table.  k' = ci*18 + t
// ---------------------------------------------------------------------------
__global__ void k_kdec() {
    int kp = blockIdx.x * 256 + threadIdx.x;
    if (kp >= KEDGE) return;
    int ci = kp / 18, t = kp - ci*18;
    int dy, dx;
    if (t < 9) { dy = t/3 - 1; dx = t%3 - 1; }
    else { int u = t - 9; dy = (u/3)*2 - 2; dx = (u%3)*2 - 2; }
    g_kdec[kp] = ci | ((dy+2) << 8) | ((dx+2) << 12);
}

// ---------------------------------------------------------------------------
// Build gA: alpha-folded conv weights in exact swizzled A-tile layout (tf32).
// ---------------------------------------------------------------------------
__global__ void k_combine_tiles(const float* __restrict__ w3, const float* __restrict__ wd3) {
    int idx = blockIdx.x * 256 + threadIdx.x;     // < 8*72*128*32 = 2359296
    int kk = idx & 31;
    int r  = idx >> 5;
    int co = r & 127;
    int et = r >> 7;                               // e*72 + tile
    int e  = et / 72, tl = et - e*72;
    int kp = tl*32 + kk;
    int ci = kp / 18, t = kp - ci*18;
    float a = (t < 9) ? g_asoft[e*5+1] : g_asoft[e*5+2];
    int tt  = (t < 9) ? t : t - 9;
    float val = a * ((t < 9 ? w3 : wd3)[((e*C + co)*C + ci)*9 + tt]);
    uint32_t off = SW128((uint32_t)(co*128 + kk*4));
    *(uint32_t*)((char*)gA + (size_t)et*TILE_BYTES + off) = f2tf32(val);
}

// ---------------------------------------------------------------------------
// Build g_wcomb for the FFMA fallback: [e][ci][tap 0..17][co]
// ---------------------------------------------------------------------------
__global__ void k_combine_wcomb(const float* __restrict__ w3, const float* __restrict__ wd3) {
    int idx = blockIdx.x * 256 + threadIdx.x;     // e*16384 + ci*128 + co
    if (idx >= 8*C*C) return;
    int e  = idx >> 14;
    int r  = idx & 16383;
    int ci = r >> 7;
    int co = r & 127;
    float a1 = g_asoft[e*5+1], a2 = g_asoft[e*5+2];
    int wb = ((e*C + co)*C + ci)*9;
    int ob = ((e*C + ci)*18)*C + co;
    #pragma unroll
    for (int k = 0; k < 9; k++) g_wcomb[ob + k*C]     = a1 * w3[wb + k];
    #pragma unroll
    for (int k = 0; k < 9; k++) g_wcomb[ob + (9+k)*C] = a2 * wd3[wb + k];
}

// ---------------------------------------------------------------------------
// 1x1 pre-conv
// ---------------------------------------------------------------------------
__global__ __launch_bounds__(256) void k_pre(const float* __restrict__ in,
                                             const float* __restrict__ w,
                                             float* __restrict__ out) {
    __shared__ __align__(16) float tin[8][HW];
    __shared__ float tw[8][16];
    int b   = blockIdx.x >> 3;
    int co0 = (blockIdx.x & 7) << 4;
    int tid = threadIdx.x;
    int px0 = tid * 4;
    const float* inb = in + b*C*HW;
    float acc[16][4] = {};
    for (int cic = 0; cic < C; cic += 8) {
        __syncthreads();
        #pragma unroll
        for (int k = 0; k < 8; k++) {
            int f = tid + k*256;
            ((float4*)tin)[f] = ((const float4*)(inb + cic*HW))[f];
        }
        if (tid < 128) {
            int ci = tid >> 4, co = tid & 15;
            tw[ci][co] = w[(co0+co)*C + cic + ci];
        }
        __syncthreads();
        #pragma unroll
        for (int ci = 0; ci < 8; ci++) {
            float4 i4 = *(const float4*)&tin[ci][px0];
            float iv[4] = {i4.x, i4.y, i4.z, i4.w};
            #pragma unroll
            for (int co = 0; co < 16; co++) {
                float wv = tw[ci][co];
                #pragma unroll
                for (int j = 0; j < 4; j++) acc[co][j] += wv * iv[j];
            }
        }
    }
    float* ob = out + (b*C + co0)*HW + px0;
    #pragma unroll
    for (int co = 0; co < 16; co++)
        *(float4*)(ob + co*HW) = make_float4(acc[co][0], acc[co][1], acc[co][2], acc[co][3]);
}

// ---------------------------------------------------------------------------
// tcgen05 tf32 implicit-GEMM node kernel (empty if feature unavailable).
// block = (b, 128-px chunk).  D[co=128][px=128] in TMEM, K = 144 tiles of 32.
// ---------------------------------------------------------------------------
__global__ __launch_bounds__(256) void k_node_mma(
    const float* __restrict__ h0, int h0bs,
    const float* __restrict__ h1, int h1bs,
    float* __restrict__ outR, int eA, int eB)
{
#if HAS_TC05
    extern __shared__ char dsm_raw[];
    char* dsm = (char*)(((uintptr_t)dsm_raw + 1023) & ~(uintptr_t)1023);
    __shared__ __align__(16) uint64_t mbar[2];
    __shared__ uint32_t tmem_ptr_s;

    const int tid = threadIdx.x;
    const int wid = tid >> 5;
    const int b   = blockIdx.x >> 3;
    const int pc  = blockIdx.x & 7;

    if (wid == 0) {
        TC_ALLOC(smem_u32(&tmem_ptr_s), 128);
        TC_RELINQ();
    }
    if (tid == 0) {
        mbar_init(smem_u32(&mbar[0]), 1);
        mbar_init(smem_u32(&mbar[1]), 1);
    }
    __syncthreads();
    const uint32_t tmem = tmem_ptr_s;
    const uint32_t mb0 = smem_u32(&mbar[0]);
    const uint32_t mb1 = smem_u32(&mbar[1]);

    const int px    = tid & 127;
    const int ybase = pc*4 + (px >> 5);
    const int x     = px & 31;
    const float* hA = h0 + (long long)b * h0bs;
    const float* hB = h1 + (long long)b * h1bs;

    int ph0 = 0, ph1 = 0;

    for (int t = 0; t < NTILES; t++) {
        const int buf = t & 1;
        const uint32_t mb = buf ? mb1 : mb0;
        if (t >= 2) {
            if (buf) { mbar_wait(mb1, ph1); ph1 ^= 1; }
            else     { mbar_wait(mb0, ph0); ph0 ^= 1; }
        }
        const int e  = (t < NTILE_EDGE) ? eA : eB;
        const int te = (t < NTILE_EDGE) ? t : t - NTILE_EDGE;
        // ---- A tile copy (pre-swizzled tf32 in global) ----
        {
            const uint4* src = (const uint4*)((const char*)gA + (size_t)(e*NTILE_EDGE + te)*TILE_BYTES);
            uint4* dst = (uint4*)(dsm + buf*32768);
            #pragma unroll
            for (int j = 0; j < 4; j++) dst[tid + j*256] = src[tid + j*256];
        }
        // ---- B tile im2col build ----
        {
            const float* hb = (t < NTILE_EDGE) ? hA : hB;
            char* Bd = dsm + buf*32768 + TILE_BYTES;
            const int kbase = te * 32;
            #pragma unroll
            for (int it = 0; it < 4; it++) {
                int g = it*2 + (tid >> 7);
                uint32_t v[4];
                #pragma unroll
                for (int q = 0; q < 4; q++) {
                    int dec = g_kdec[kbase + g*4 + q];
                    int ci = dec & 255;
                    int yy = ybase + ((dec >> 8) & 15) - 2;
                    int xx = x + ((dec >> 12) & 15) - 2;
                    float f = 0.f;
                    if ((unsigned)yy < 32u && (unsigned)xx < 32u)
                        f = __ldg(&hb[ci*HW + yy*32 + xx]);
                    v[q] = f2tf32(f);
                }
                uint32_t off = SW128((uint32_t)(px*128 + g*16));
                *(uint4*)(Bd + off) = make_uint4(v[0], v[1], v[2], v[3]);
            }
        }
        __syncthreads();
        if (wid == 0 && elect_one()) {
            FENCE_ASYNC();
            uint64_t ad = make_desc(smem_u32(dsm + buf*32768));
            uint64_t bd = make_desc(smem_u32(dsm + buf*32768 + TILE_BYTES));
            #pragma unroll
            for (int k = 0; k < 4; k++)
                mma_tf32_ss(tmem, ad + k*2, bd + k*2, IDESC_TF32,
                            (t == 0 && k == 0) ? 0u : 1u);
            tmem_commit(mb);
        }
    }
    mbar_wait(mb1, ph1);
    TC_FENCE_AFTER();

    // ---- epilogue: 8 warps read TMEM, write fp32 into concat layout ----
    {
        const int wg  = tid & 127;
        const uint32_t woff = ((uint32_t)(wg >> 5)) << 21;
        const int co  = ((wg >> 5) << 5) + (tid & 31);
        const int cb  = (tid >= 128) ? 64 : 0;
        float* op = outR + (long long)b*OUT_BSTRIDE + co*HW + pc*128 + cb;
        uint32_t r[32];
        LD_X32(r, tmem + cb + woff);
        TC_WAIT_LD();
        #pragma unroll
        for (int j = 0; j < 8; j++)
            ((float4*)op)[j] = make_float4(__uint_as_float(r[j*4+0]), __uint_as_float(r[j*4+1]),
                                           __uint_as_float(r[j*4+2]), __uint_as_float(r[j*4+3]));
        LD_X32(r, tmem + cb + 32 + woff);
        TC_WAIT_LD();
        #pragma unroll
        for (int j = 0; j < 8; j++)
            ((float4*)(op + 32))[j] = make_float4(__uint_as_float(r[j*4+0]), __uint_as_float(r[j*4+1]),
                                                  __uint_as_float(r[j*4+2]), __uint_as_float(r[j*4+3]));
        TC_FENCE_BEFORE();
    }
    __syncthreads();
    if (tid == 0) { mbar_inval(mb0); mbar_inval(mb1); }
    __syncthreads();
    if (wid == 0) TC_DEALLOC(tmem, 128);
#endif  // HAS_TC05
}

// ---------------------------------------------------------------------------
// FFMA fallback node kernel (round-1 conv path; empty when tcgen05 exists).
// block = (b, 16-co chunk); thread = row y, 4 consecutive x.
// Writes conv contribution only (identity/avg/max handled by k_pool RMW).
// ---------------------------------------------------------------------------
__global__ __launch_bounds__(256) void k_node_ffma(
    const float* __restrict__ h0, int h0_bs,
    const float* __restrict__ h1, int h1_bs,
    float* __restrict__ out, int eA, int eB)
{
#if !HAS_TC05
    __shared__ __align__(16) float tile[4][36*37];
    __shared__ __align__(16) float wsh[4][18][16];
    const int tid = threadIdx.x;
    const int b   = blockIdx.x >> 3;
    const int co0 = (blockIdx.x & 7) << 4;
    const int y   = tid >> 3;
    const int x0  = (tid & 7) << 2;
    float acc[16][4] = {};

    const int DY[18] = {-1,-1,-1, 0,0,0, 1,1,1,  -2,-2,-2, 0,0,0, 2,2,2};
    const int DX[18] = {-1, 0, 1,-1,0,1,-1,0,1,  -2, 0, 2,-2,0,2,-2,0,2};

    for (int s = 0; s < 2; s++) {
        const float* hb = s ? (h1 + (long long)b*h1_bs) : (h0 + (long long)b*h0_bs);
        const int e = s ? eB : eA;
        for (int cic = 0; cic < C; cic += 4) {
            __syncthreads();
            for (int i = tid; i < 4*1296; i += 256) {
                int ci = i / 1296, r = i - ci*1296;
                int ty = r / 36,  tx = r - ty*36;
                int gy = ty - 2,  gx = tx - 2;
                float v = 0.f;
                if ((unsigned)gy < 32u && (unsigned)gx < 32u)
                    v = hb[(cic + ci)*HW + gy*32 + gx];
                tile[ci][ty*37 + tx] = v;
            }
            for (int i = tid; i < 4*18*16; i += 256) {
                int ci = i / 288, r = i - ci*288;
                int t = r >> 4, co = r & 15;
                wsh[ci][t][co] = g_wcomb[((e*C + cic + ci)*18 + t)*C + co0 + co];
            }
            __syncthreads();
            #pragma unroll 1
            for (int ci = 0; ci < 4; ci++) {
                const float* tc = &tile[ci][(y+2)*37 + (x0+2)];
                #pragma unroll
                for (int t = 0; t < 18; t++) {
                    const float* tp = tc + DY[t]*37 + DX[t];
                    float in4[4] = {tp[0], tp[1], tp[2], tp[3]};
                    const float4* wp = (const float4*)wsh[ci][t];
                    float wv[16];
                    #pragma unroll
                    for (int q = 0; q < 4; q++) {
                        float4 w = wp[q];
                        wv[q*4+0] = w.x; wv[q*4+1] = w.y; wv[q*4+2] = w.z; wv[q*4+3] = w.w;
                    }
                    #pragma unroll
                    for (int co = 0; co < 16; co++)
                        #pragma unroll
                        for (int j = 0; j < 4; j++)
                            acc[co][j] += wv[co] * in4[j];
                }
            }
        }
    }
    float* ob = out + (long long)b*OUT_BSTRIDE + co0*HW + y*32 + x0;
    #pragma unroll
    for (int co = 0; co < 16; co++)
        *(float4*)(ob + co*HW) = make_float4(acc[co][0], acc[co][1], acc[co][2], acc[co][3]);
#endif  // !HAS_TC05
}

// ---------------------------------------------------------------------------
// identity + avg3 + max3 terms (exact fp32), RMW into out region.
// ---------------------------------------------------------------------------
__global__ __launch_bounds__(256) void k_pool(
    const float* __restrict__ h0, int h0bs,
    const float* __restrict__ h1, int h1bs,
    float* __restrict__ outR, int eA, int eB)
{
    __shared__ float tl[8][34*36];
    const int b  = blockIdx.x >> 5;
    const int c0 = (blockIdx.x & 31) << 2;
    const int tid = threadIdx.x;

    for (int i = tid; i < 8*34*36; i += 256) ((float*)tl)[i] = 0.f;
    __syncthreads();
    for (int i = tid; i < 8*HW; i += 256) {
        int e = i >> 12, ch = (i >> 10) & 3, p = i & 1023;
        int y = p >> 5, xx = p & 31;
        const float* hb = e ? (h1 + (long long)b*h1bs) : (h0 + (long long)b*h0bs);
        tl[e*4+ch][(y+1)*36 + xx + 1] = hb[(c0+ch)*HW + p];
    }
    __syncthreads();

    float a0[2], a3[2], a4[2];
    a0[0] = g_asoft[eA*5+0]; a3[0] = g_asoft[eA*5+3]*(1.f/9.f); a4[0] = g_asoft[eA*5+4];
    a0[1] = g_asoft[eB*5+0]; a3[1] = g_asoft[eB*5+3]*(1.f/9.f); a4[1] = g_asoft[eB*5+4];

    const int ch = tid >> 6;
    float* op = outR + (long long)b*OUT_BSTRIDE + (c0+ch)*HW;
    #pragma unroll 4
    for (int j = 0; j < 16; j++) {
        int p = (tid & 63) + j*64;
        int y = p >> 5, xx = p & 31;
        int base = (y+1)*36 + xx + 1;
        float acc = 0.f;
        #pragma unroll
        for (int e = 0; e < 2; e++) {
            const float* tc = tl[e*4+ch];
            float cv = tc[base];
            float sum = 0.f, mx = -INFINITY;
            #pragma unroll
            for (int dy = -1; dy <= 1; dy++)
                #pragma unroll
                for (int dx = -1; dx <= 1; dx++) {
                    float v = tc[base + dy*36 + dx];
                    sum += v;
                    bool ok = ((unsigned)(y+dy) < 32u) && ((unsigned)(xx+dx) < 32u);
                    if (ok) mx = fmaxf(mx, v);
                }
            acc += a0[e]*cv + a3[e]*sum + a4[e]*mx;
        }
        op[p] += acc;
    }
}

// ---------------------------------------------------------------------------
__global__ void k_copy_skip(const float* __restrict__ skip,
                            float* __restrict__ out,
                            float* __restrict__ out2) {
    int i = blockIdx.x * 256 + threadIdx.x;
    if (i >= (BATCH*C*HW)/4) return;
    float4 v = ((const float4*)skip)[i];
    int pe = i * 4;
    int b  = pe >> 17;
    int r  = pe & (C*HW - 1);
    *(float4*)(out + (long long)b*OUT_BSTRIDE + 4*C*HW + r) = v;
    if (out2) ((float4*)out2)[i] = v;
}

// ---------------------------------------------------------------------------
static void launch_node(const float* h0, int h0bs, const float* h1, int h1bs,
                        float* outR, int eA, int eB, int dsmem) {
    k_node_mma <<<BATCH*8, 256, dsmem>>>(h0, h0bs, h1, h1bs, outR, eA, eB);
    k_node_ffma<<<BATCH*8, 256>>>       (h0, h0bs, h1, h1bs, outR, eA, eB);
    k_pool     <<<BATCH*32, 256>>>      (h0, h0bs, h1, h1bs, outR, eA, eB);
}

extern "C" void kernel_launch(void* const* d_in, const int* in_sizes, int n_in,
                              void* d_out, int out_size) {
    const float* input0 = (const float*)d_in[0];
    const float* input1 = (const float*)d_in[1];
    const float* skip   = (const float*)d_in[2];
    const float* w_pre0 = (const float*)d_in[3];
    const float* w_pre1 = (const float*)d_in[4];
    const float* w3     = (const float*)d_in[5];
    const float* wd3    = (const float*)d_in[6];
    const float* alphas = (const float*)d_in[7];
    float* out = (float*)d_out;

    float *s0, *s1;
    cudaGetSymbolAddress((void**)&s0, g_s0);
    cudaGetSymbolAddress((void**)&s1, g_s1);

    const int DSMEM = 4*TILE_BYTES + 1024;
    cudaFuncSetAttribute(k_node_mma, cudaFuncAttributeMaxDynamicSharedMemorySize, DSMEM);

    k_softmax<<<1, 8>>>(alphas);
    k_kdec<<<(KEDGE + 255)/256, 256>>>();
    k_combine_tiles<<<(8*NTILE_EDGE*TILE_FLOATS)/256, 256>>>(w3, wd3);
    k_combine_wcomb<<<(8*C*C + 255)/256, 256>>>(w3, wd3);
    k_pre<<<BATCH*8, 256>>>(input0, w_pre0, s0);
    k_pre<<<BATCH*8, 256>>>(input1, w_pre1, s1);

    launch_node(s0, REG_STRIDE, s1, REG_STRIDE,                         out + 0*C*HW, 0, 1, DSMEM);
    launch_node(s1, REG_STRIDE, out + 0*C*HW, OUT_BSTRIDE,              out + 1*C*HW, 2, 3, DSMEM);
    launch_node(out + 0*C*HW, OUT_BSTRIDE, out + 1*C*HW, OUT_BSTRIDE,   out + 2*C*HW, 4, 5, DSMEM);
    launch_node(out + 1*C*HW, OUT_BSTRIDE, out + 2*C*HW, OUT_BSTRIDE,   out + 3*C*HW, 6, 7, DSMEM);

    long long concat_elems = (long long)BATCH*OUTC*HW;
    long long skip_elems   = (long long)BATCH*C*HW;
    float* out2 = nullptr;
    if ((long long)out_size >= concat_elems + skip_elems)
        out2 = out + concat_elems;
    k_copy_skip<<<((BATCH*C*HW/4) + 255)/256, 256>>>(skip, out, out2);
}

// round 4
// speedup vs baseline: 3.6692x; 1.6155x over previous
#include <cuda_runtime.h>
#include <math.h>
#include <stdint.h>

#define BATCH 64
#define C 128
#define HW 1024
#define OUTC 640
#define REG_STRIDE (C*HW)
#define OUT_BSTRIDE (OUTC*HW)

#define KEDGE 2304            // 128 ci * 18 taps
#define NTILE_EDGE 72         // 2304 / 32
#define NTILES 144            // 2 edges
#define TILE_FLOATS 4096      // 128 rows * 32 k
#define TILE_BYTES 16384

// idesc for kind::tf32: dtype=F32(bit4), atype=TF32=2(bits7-9), btype=TF32=2(bits10-12),
// N=128 -> (128/8)<<17, M=128 -> (128/16)<<24
#define IDESC_TF32 0x8200910u

// tcgen05 only legal in the arch-conditional (sm_103a) pass; other passes get
// empty kernels (the 'a' pass is proven to exist on this bench as of R3).
#if defined(__CUDA_ARCH_FEAT_SM103_ALL) || defined(__CUDA_ARCH_FEAT_SM100_ALL) || \
    (defined(__CUDA_ARCH_SPECIFIC__) && (__CUDA_ARCH_SPECIFIC__ >= 1000))
#define HAS_TC05 1
#else
#define HAS_TC05 0
#endif

__device__ float g_s0[BATCH*C*HW];
__device__ float g_s1[BATCH*C*HW];
__device__ __align__(16) uint32_t gA[8*NTILE_EDGE*TILE_FLOATS];  // tf32 bits, swizzled A-tiles
__device__ int   g_kdec[KEDGE];
__device__ float g_asoft[8*5];

// ---------------------------------------------------------------------------
// generic helpers
// ---------------------------------------------------------------------------
__device__ __forceinline__ uint32_t smem_u32(const void* p) {
    uint32_t a;
    asm("{ .reg .u64 t; cvta.to.shared.u64 t, %1; cvt.u32.u64 %0, t; }" : "=r"(a) : "l"(p));
    return a;
}
#define SW128(o) ((o) ^ (((o) >> 3) & 0x70))
__device__ __forceinline__ uint32_t f2tf32(float f) {
    uint32_t r;
    asm("cvt.rna.tf32.f32 %0, %1;" : "=r"(r) : "f"(f));
    return r;
}

#if HAS_TC05
// ---------------------------------------------------------------------------
// tcgen05 / bulk-async PTX helpers
// ---------------------------------------------------------------------------
__device__ __forceinline__ uint32_t elect_one() {
    uint32_t p;
    asm volatile("{ .reg .pred p; elect.sync _|p, 0xFFFFFFFF; selp.b32 %0, 1, 0, p; }" : "=r"(p));
    return p;
}
__device__ __forceinline__ uint64_t make_desc(uint32_t addr) {
    // SW128, version=1(Blackwell), SBO=64, LBO=1  (K-major)
    const uint64_t base = (uint64_t(2) << 61) | (uint64_t(1) << 46)
                        | (uint64_t(64) << 32) | (uint64_t(1) << 16);
    return base | ((uint64_t)(addr >> 4) & 0x3FFF);
}
__device__ __forceinline__ void mma_tf32_ss(uint32_t d, uint64_t ad, uint64_t bd,
                                            uint32_t idesc, uint32_t en) {
    asm volatile(
        "{\n\t.reg .pred p;\n\tsetp.ne.u32 p, %5, 0;\n\t"
        "tcgen05.mma.cta_group::1.kind::tf32 [%0], %1, %2, %3, {%4, %4, %4, %4}, p;\n\t}"
        :: "r"(d), "l"(ad), "l"(bd), "r"(idesc), "r"(0u), "r"(en) : "memory");
}
__device__ __forceinline__ void mbar_init(uint32_t a, uint32_t cnt) {
    asm volatile("mbarrier.init.shared.b64 [%0], %1;" :: "r"(a), "r"(cnt) : "memory");
}
__device__ __forceinline__ void mbar_inval(uint32_t a) {
    asm volatile("mbarrier.inval.shared.b64 [%0];" :: "r"(a) : "memory");
}
__device__ __forceinline__ void mbar_wait(uint32_t a, uint32_t parity) {
    asm volatile(
        "{\n\t.reg .pred P;\n"
        "W_%=:\n\t"
        "mbarrier.try_wait.parity.acquire.cta.shared::cta.b64 P, [%0], %1, 0x989680;\n\t"
        "@P bra D_%=;\n\tbra W_%=;\nD_%=:\n\t}"
        :: "r"(a), "r"(parity) : "memory");
}
__device__ __forceinline__ void mbar_expect_tx(uint32_t a, uint32_t bytes) {
    asm volatile("mbarrier.arrive.expect_tx.shared.b64 _, [%0], %1;"
                 :: "r"(a), "r"(bytes) : "memory");
}
__device__ __forceinline__ void bulk_g2s(uint32_t dst, const void* src,
                                         uint32_t bytes, uint32_t mbar) {
    asm volatile(
        "cp.async.bulk.shared::cta.global.mbarrier::complete_tx::bytes [%0], [%1], %2, [%3];"
        :: "r"(dst), "l"(src), "r"(bytes), "r"(mbar) : "memory");
}
__device__ __forceinline__ void tmem_commit(uint32_t mbar) {
    asm volatile(
        "tcgen05.commit.cta_group::1.mbarrier::arrive::one.shared::cluster.b64 [%0];"
        :: "r"(mbar) : "memory");
}
#define TC_ALLOC(dst, n)   asm volatile("tcgen05.alloc.cta_group::1.sync.aligned.shared::cta.b32 [%0], %1;" :: "r"(dst), "r"(n) : "memory")
#define TC_DEALLOC(t, n)   asm volatile("tcgen05.dealloc.cta_group::1.sync.aligned.b32 %0, %1;" :: "r"(t), "r"(n))
#define TC_RELINQ()        asm volatile("tcgen05.relinquish_alloc_permit.cta_group::1.sync.aligned;")
#define TC_FENCE_AFTER()   asm volatile("tcgen05.fence::after_thread_sync;" ::: "memory")
#define TC_FENCE_BEFORE()  asm volatile("tcgen05.fence::before_thread_sync;" ::: "memory")
#define TC_WAIT_LD()       asm volatile("tcgen05.wait::ld.sync.aligned;" ::: "memory")
#define FENCE_ASYNC()      asm volatile("fence.proxy.async.shared::cta;" ::: "memory")

#define LD_X32(r, a) \
    asm volatile("tcgen05.ld.sync.aligned.32x32b.x32.b32 " \
        "{%0,%1,%2,%3,%4,%5,%6,%7,%8,%9,%10,%11,%12,%13,%14,%15," \
        "%16,%17,%18,%19,%20,%21,%22,%23,%24,%25,%26,%27,%28,%29,%30,%31}, [%32];" \
        : "=r"((r)[0]),"=r"((r)[1]),"=r"((r)[2]),"=r"((r)[3]), \
          "=r"((r)[4]),"=r"((r)[5]),"=r"((r)[6]),"=r"((r)[7]), \
          "=r"((r)[8]),"=r"((r)[9]),"=r"((r)[10]),"=r"((r)[11]), \
          "=r"((r)[12]),"=r"((r)[13]),"=r"((r)[14]),"=r"((r)[15]), \
          "=r"((r)[16]),"=r"((r)[17]),"=r"((r)[18]),"=r"((r)[19]), \
          "=r"((r)[20]),"=r"((r)[21]),"=r"((r)[22]),"=r"((r)[23]), \
          "=r"((r)[24]),"=r"((r)[25]),"=r"((r)[26]),"=r"((r)[27]), \
          "=r"((r)[28]),"=r"((r)[29]),"=r"((r)[30]),"=r"((r)[31]) \
        : "r"(a))
#endif  // HAS_TC05

// ---------------------------------------------------------------------------
// softmax over alphas (8 edges x 5 ops)
// ---------------------------------------------------------------------------
__global__ void k_softmax(const float* __restrict__ alphas) {
    int e = threadIdx.x;
    if (e < 8) {
        float m = -1e30f;
        #pragma unroll
        for (int i = 0; i < 5; i++) m = fmaxf(m, alphas[e*5+i]);
        float ex[5]; float s = 0.f;
        #pragma unroll
        for (int i = 0; i < 5; i++) { ex[i] = expf(alphas[e*5+i] - m); s += ex[i]; }
        float inv = 1.f / s;
        #pragma unroll
        for (int i = 0; i < 5; i++) g_asoft[e*5+i] = ex[i] * inv;
    }
}

// ---------------------------------------------------------------------------
// k' -> (ci, dy, dx) decode table.  k' = ci*18 + t
// ---------------------------------------------------------------------------
__global__ void k_kdec() {
    int kp = blockIdx.x * 256 + threadIdx.x;
    if (kp >= KEDGE) return;
    int ci = kp / 18, t = kp - ci*18;
    int dy, dx;
    if (t < 9) { dy = t/3 - 1; dx = t%3 - 1; }
    else { int u = t - 9; dy = (u/3)*2 - 2; dx = (u%3)*2 - 2; }
    g_kdec[kp] = ci | ((dy+2) << 8) | ((dx+2) << 12);
}

// ---------------------------------------------------------------------------
// Build gA: alpha-folded conv weights in exact swizzled A-tile layout (tf32).
// ---------------------------------------------------------------------------
__global__ void k_combine_tiles(const float* __restrict__ w3, const float* __restrict__ wd3) {
    int idx = blockIdx.x * 256 + threadIdx.x;     // < 8*72*128*32 = 2359296
    int kk = idx & 31;
    int r  = idx >> 5;
    int co = r & 127;
    int et = r >> 7;                               // e*72 + tile
    int e  = et / 72, tl = et - e*72;
    int kp = tl*32 + kk;
    int ci = kp / 18, t = kp - ci*18;
    float a = (t < 9) ? g_asoft[e*5+1] : g_asoft[e*5+2];
    int tt  = (t < 9) ? t : t - 9;
    float val = a * ((t < 9 ? w3 : wd3)[((e*C + co)*C + ci)*9 + tt]);
    uint32_t off = SW128((uint32_t)(co*128 + kk*4));
    *(uint32_t*)((char*)gA + (size_t)et*TILE_BYTES + off) = f2tf32(val);
}

// ---------------------------------------------------------------------------
// 1x1 pre-conv
// ---------------------------------------------------------------------------
__global__ __launch_bounds__(256) void k_pre(const float* __restrict__ in,
                                             const float* __restrict__ w,
                                             float* __restrict__ out) {
    __shared__ __align__(16) float tin[8][HW];
    __shared__ float tw[8][16];
    int b   = blockIdx.x >> 3;
    int co0 = (blockIdx.x & 7) << 4;
    int tid = threadIdx.x;
    int px0 = tid * 4;
    const float* inb = in + b*C*HW;
    float acc[16][4] = {};
    for (int cic = 0; cic < C; cic += 8) {
        __syncthreads();
        #pragma unroll
        for (int k = 0; k < 8; k++) {
            int f = tid + k*256;
            ((float4*)tin)[f] = ((const float4*)(inb + cic*HW))[f];
        }
        if (tid < 128) {
            int ci = tid >> 4, co = tid & 15;
            tw[ci][co] = w[(co0+co)*C + cic + ci];
        }
        __syncthreads();
        #pragma unroll
        for (int ci = 0; ci < 8; ci++) {
            float4 i4 = *(const float4*)&tin[ci][px0];
            float iv[4] = {i4.x, i4.y, i4.z, i4.w};
            #pragma unroll
            for (int co = 0; co < 16; co++) {
                float wv = tw[ci][co];
                #pragma unroll
                for (int j = 0; j < 4; j++) acc[co][j] += wv * iv[j];
            }
        }
    }
    float* ob = out + (b*C + co0)*HW + px0;
    #pragma unroll
    for (int co = 0; co < 16; co++)
        *(float4*)(ob + co*HW) = make_float4(acc[co][0], acc[co][1], acc[co][2], acc[co][3]);
}

// ---------------------------------------------------------------------------
// tcgen05 tf32 implicit-GEMM node kernel.
// block = (b, 128-px chunk).  D[co=128][px=128] in TMEM, K = 144 tiles of 32.
// A tiles arrive via cp.async.bulk (pre-swizzled in gA); B tiles are im2col
// built by the threads. Double-buffered; MMA completion tracked via commit.
// ---------------------------------------------------------------------------
__global__ __launch_bounds__(256) void k_node_mma(
    const float* __restrict__ h0, int h0bs,
    const float* __restrict__ h1, int h1bs,
    float* __restrict__ outR, int eA, int eB)
{
#if HAS_TC05
    extern __shared__ char dsm_raw[];
    char* dsm = (char*)(((uintptr_t)dsm_raw + 1023) & ~(uintptr_t)1023);
    // layout: A0 @0, B0 @16K, A1 @32K, B1 @48K
    __shared__ __align__(16) uint64_t mbar[2];   // MMA-done per buffer
    __shared__ __align__(16) uint64_t abar[2];   // A-tile-arrived per buffer
    __shared__ uint32_t tmem_ptr_s;

    const int tid = threadIdx.x;
    const int wid = tid >> 5;
    const int b   = blockIdx.x >> 3;
    const int pc  = blockIdx.x & 7;

    if (wid == 0) {
        TC_ALLOC(smem_u32(&tmem_ptr_s), 128);
        TC_RELINQ();
    }
    if (tid == 0) {
        mbar_init(smem_u32(&mbar[0]), 1);
        mbar_init(smem_u32(&mbar[1]), 1);
        mbar_init(smem_u32(&abar[0]), 1);
        mbar_init(smem_u32(&abar[1]), 1);
    }
    __syncthreads();
    const uint32_t tmem = tmem_ptr_s;
    const uint32_t mb0 = smem_u32(&mbar[0]);
    const uint32_t mb1 = smem_u32(&mbar[1]);
    const uint32_t ab0 = smem_u32(&abar[0]);
    const uint32_t ab1 = smem_u32(&abar[1]);

    const bool leader = (wid == 0) && elect_one();

    const int px    = tid & 127;
    const int ybase = pc*4 + (px >> 5);
    const int x     = px & 31;
    const float* hA = h0 + (long long)b * h0bs;
    const float* hB = h1 + (long long)b * h1bs;

    int ph0 = 0, ph1 = 0;      // MMA-done phases
    int aph0 = 0, aph1 = 0;    // A-arrival phases

    for (int t = 0; t < NTILES; t++) {
        const int buf = t & 1;
        const uint32_t mb = buf ? mb1 : mb0;
        const uint32_t ab = buf ? ab1 : ab0;
        if (t >= 2) {
            if (buf) { mbar_wait(mb1, ph1); ph1 ^= 1; }
            else     { mbar_wait(mb0, ph0); ph0 ^= 1; }
        }
        const int e  = (t < NTILE_EDGE) ? eA : eB;
        const int te = (t < NTILE_EDGE) ? t : t - NTILE_EDGE;
        // ---- A tile: async bulk copy of pre-swizzled tf32 tile ----
        if (leader) {
            mbar_expect_tx(ab, TILE_BYTES);
            bulk_g2s(smem_u32(dsm + buf*32768),
                     (const char*)gA + (size_t)(e*NTILE_EDGE + te)*TILE_BYTES,
                     TILE_BYTES, ab);
        }
        // ---- B tile im2col build ----
        {
            const float* hb = (t < NTILE_EDGE) ? hA : hB;
            char* Bd = dsm + buf*32768 + TILE_BYTES;
            const int kbase = te * 32;
            #pragma unroll
            for (int it = 0; it < 4; it++) {
                int g = it*2 + (tid >> 7);
                uint32_t v[4];
                #pragma unroll
                for (int q = 0; q < 4; q++) {
                    int dec = g_kdec[kbase + g*4 + q];
                    int ci = dec & 255;
                    int yy = ybase + ((dec >> 8) & 15) - 2;
                    int xx = x + ((dec >> 12) & 15) - 2;
                    float f = 0.f;
                    if ((unsigned)yy < 32u && (unsigned)xx < 32u)
                        f = __ldg(&hb[ci*HW + yy*32 + xx]);
                    v[q] = f2tf32(f);
                }
                uint32_t off = SW128((uint32_t)(px*128 + g*16));
                *(uint4*)(Bd + off) = make_uint4(v[0], v[1], v[2], v[3]);
            }
        }
        __syncthreads();
        if (leader) {
            FENCE_ASYNC();
            if (buf) { mbar_wait(ab1, aph1); aph1 ^= 1; }
            else     { mbar_wait(ab0, aph0); aph0 ^= 1; }
            uint64_t ad = make_desc(smem_u32(dsm + buf*32768));
            uint64_t bd = make_desc(smem_u32(dsm + buf*32768 + TILE_BYTES));
            #pragma unroll
            for (int k = 0; k < 4; k++)
                mma_tf32_ss(tmem, ad + k*2, bd + k*2, IDESC_TF32,
                            (t == 0 && k == 0) ? 0u : 1u);
            tmem_commit(mb);
        }
    }
    // final wait: last commit (tile 143, buf 1) covers all prior MMAs
    mbar_wait(mb1, ph1);
    TC_FENCE_AFTER();

    // ---- epilogue: 8 warps read TMEM, write fp32 into concat layout ----
    {
        const int wg  = tid & 127;
        const uint32_t woff = ((uint32_t)(wg >> 5)) << 21;
        const int co  = ((wg >> 5) << 5) + (tid & 31);
        const int cb  = (tid >= 128) ? 64 : 0;
        float* op = outR + (long long)b*OUT_BSTRIDE + co*HW + pc*128 + cb;
        uint32_t r[32];
        LD_X32(r, tmem + cb + woff);
        TC_WAIT_LD();
        #pragma unroll
        for (int j = 0; j < 8; j++)
            ((float4*)op)[j] = make_float4(__uint_as_float(r[j*4+0]), __uint_as_float(r[j*4+1]),
                                           __uint_as_float(r[j*4+2]), __uint_as_float(r[j*4+3]));
        LD_X32(r, tmem + cb + 32 + woff);
        TC_WAIT_LD();
        #pragma unroll
        for (int j = 0; j < 8; j++)
            ((float4*)(op + 32))[j] = make_float4(__uint_as_float(r[j*4+0]), __uint_as_float(r[j*4+1]),
                                                  __uint_as_float(r[j*4+2]), __uint_as_float(r[j*4+3]));
        TC_FENCE_BEFORE();
    }
    __syncthreads();
    if (tid == 0) { mbar_inval(mb0); mbar_inval(mb1); mbar_inval(ab0); mbar_inval(ab1); }
    __syncthreads();
    if (wid == 0) TC_DEALLOC(tmem, 128);
#endif  // HAS_TC05
}

// ---------------------------------------------------------------------------
// identity + avg3 + max3 terms (exact fp32), RMW into out region.
// ---------------------------------------------------------------------------
__global__ __launch_bounds__(256) void k_pool(
    const float* __restrict__ h0, int h0bs,
    const float* __restrict__ h1, int h1bs,
    float* __restrict__ outR, int eA, int eB)
{
    __shared__ float tl[8][34*36];
    const int b  = blockIdx.x >> 5;
    const int c0 = (blockIdx.x & 31) << 2;
    const int tid = threadIdx.x;

    for (int i = tid; i < 8*34*36; i += 256) ((float*)tl)[i] = 0.f;
    __syncthreads();
    for (int i = tid; i < 8*HW; i += 256) {
        int e = i >> 12, ch = (i >> 10) & 3, p = i & 1023;
        int y = p >> 5, xx = p & 31;
        const float* hb = e ? (h1 + (long long)b*h1bs) : (h0 + (long long)b*h0bs);
        tl[e*4+ch][(y+1)*36 + xx + 1] = hb[(c0+ch)*HW + p];
    }
    __syncthreads();

    float a0[2], a3[2], a4[2];
    a0[0] = g_asoft[eA*5+0]; a3[0] = g_asoft[eA*5+3]*(1.f/9.f); a4[0] = g_asoft[eA*5+4];
    a0[1] = g_asoft[eB*5+0]; a3[1] = g_asoft[eB*5+3]*(1.f/9.f); a4[1] = g_asoft[eB*5+4];

    const int ch = tid >> 6;
    float* op = outR + (long long)b*OUT_BSTRIDE + (c0+ch)*HW;
    #pragma unroll 4
    for (int j = 0; j < 16; j++) {
        int p = (tid & 63) + j*64;
        int y = p >> 5, xx = p & 31;
        int base = (y+1)*36 + xx + 1;
        float acc = 0.f;
        #pragma unroll
        for (int e = 0; e < 2; e++) {
            const float* tc = tl[e*4+ch];
            float cv = tc[base];
            float sum = 0.f, mx = -INFINITY;
            #pragma unroll
            for (int dy = -1; dy <= 1; dy++)
                #pragma unroll
                for (int dx = -1; dx <= 1; dx++) {
                    float v = tc[base + dy*36 + dx];
                    sum += v;
                    bool ok = ((unsigned)(y+dy) < 32u) && ((unsigned)(xx+dx) < 32u);
                    if (ok) mx = fmaxf(mx, v);
                }
            acc += a0[e]*cv + a3[e]*sum + a4[e]*mx;
        }
        op[p] += acc;
    }
}

// ---------------------------------------------------------------------------
__global__ void k_copy_skip(const float* __restrict__ skip,
                            float* __restrict__ out,
                            float* __restrict__ out2) {
    int i = blockIdx.x * 256 + threadIdx.x;
    if (i >= (BATCH*C*HW)/4) return;
    float4 v = ((const float4*)skip)[i];
    int pe = i * 4;
    int b  = pe >> 17;
    int r  = pe & (C*HW - 1);
    *(float4*)(out + (long long)b*OUT_BSTRIDE + 4*C*HW + r) = v;
    if (out2) ((float4*)out2)[i] = v;
}

// ---------------------------------------------------------------------------
static void launch_node(const float* h0, int h0bs, const float* h1, int h1bs,
                        float* outR, int eA, int eB, int dsmem) {
    k_node_mma<<<BATCH*8, 256, dsmem>>>(h0, h0bs, h1, h1bs, outR, eA, eB);
    k_pool    <<<BATCH*32, 256>>>      (h0, h0bs, h1, h1bs, outR, eA, eB);
}

extern "C" void kernel_launch(void* const* d_in, const int* in_sizes, int n_in,
                              void* d_out, int out_size) {
    const float* input0 = (const float*)d_in[0];
    const float* input1 = (const float*)d_in[1];
    const float* skip   = (const float*)d_in[2];
    const float* w_pre0 = (const float*)d_in[3];
    const float* w_pre1 = (const float*)d_in[4];
    const float* w3     = (const float*)d_in[5];
    const float* wd3    = (const float*)d_in[6];
    const float* alphas = (const float*)d_in[7];
    float* out = (float*)d_out;

    float *s0, *s1;
    cudaGetSymbolAddress((void**)&s0, g_s0);
    cudaGetSymbolAddress((void**)&s1, g_s1);

    const int DSMEM = 4*TILE_BYTES + 1024;
    cudaFuncSetAttribute(k_node_mma, cudaFuncAttributeMaxDynamicSharedMemorySize, DSMEM);

    // prologue is exactly 5 launches so the first k_node_mma lands in the
    // ncu -s 5 -c 1 capture window.
    k_softmax<<<1, 8>>>(alphas);
    k_kdec<<<(KEDGE + 255)/256, 256>>>();
    k_combine_tiles<<<(8*NTILE_EDGE*TILE_FLOATS)/256, 256>>>(w3, wd3);
    k_pre<<<BATCH*8, 256>>>(input0, w_pre0, s0);
    k_pre<<<BATCH*8, 256>>>(input1, w_pre1, s1);

    launch_node(s0, REG_STRIDE, s1, REG_STRIDE,                         out + 0*C*HW, 0, 1, DSMEM);
    launch_node(s1, REG_STRIDE, out + 0*C*HW, OUT_BSTRIDE,              out + 1*C*HW, 2, 3, DSMEM);
    launch_node(out + 0*C*HW, OUT_BSTRIDE, out + 1*C*HW, OUT_BSTRIDE,   out + 2*C*HW, 4, 5, DSMEM);
    launch_node(out + 1*C*HW, OUT_BSTRIDE, out + 2*C*HW, OUT_BSTRIDE,   out + 3*C*HW, 6, 7, DSMEM);

    long long concat_elems = (long long)BATCH*OUTC*HW;
    long long skip_elems   = (long long)BATCH*C*HW;
    float* out2 = nullptr;
    if ((long long)out_size >= concat_elems + skip_elems)
        out2 = out + concat_elems;
    k_copy_skip<<<((BATCH*C*HW/4) + 255)/256, 256>>>(skip, out, out2);
}

// round 5
// speedup vs baseline: 3.9822x; 1.0853x over previous
#include <cuda_runtime.h>
#include <math.h>
#include <stdint.h>

#define BATCH 64
#define C 128
#define HW 1024
#define OUTC 640
#define REG_STRIDE (C*HW)
#define OUT_BSTRIDE (OUTC*HW)

#define KEDGE 2304            // 128 ci * 18 taps
#define NTILE_EDGE 72         // 2304 / 32
#define NTILES 144            // 2 edges
#define TILE_FLOATS 4096      // 128 rows * 32 k (A tile)
#define TILE_BYTES 16384      // A tile bytes
#define BTILE_BYTES 32768     // B tile: 256 px rows * 128B
#define BUF_STRIDE (TILE_BYTES + BTILE_BYTES)   // 49152

// idesc kind::tf32: dtype=F32(bit4), atype=TF32(bits7-9)=2, btype=TF32(bits10-12)=2,
// N=256 -> (256/8)=32<<17, M=128 -> (128/16)=8<<24
#define IDESC_TF32_N256 ((1u<<4)|(2u<<7)|(2u<<10)|(32u<<17)|(8u<<24))

#if defined(__CUDA_ARCH_FEAT_SM103_ALL) || defined(__CUDA_ARCH_FEAT_SM100_ALL) || \
    (defined(__CUDA_ARCH_SPECIFIC__) && (__CUDA_ARCH_SPECIFIC__ >= 1000))
#define HAS_TC05 1
#else
#define HAS_TC05 0
#endif

__device__ float g_s0[BATCH*C*HW];
__device__ float g_s1[BATCH*C*HW];
__device__ __align__(16) uint32_t gA[8*NTILE_EDGE*TILE_FLOATS];  // tf32 bits, swizzled A-tiles
__device__ int   g_kdec[KEDGE];
__device__ float g_asoft[8*5];

// ---------------------------------------------------------------------------
__device__ __forceinline__ uint32_t smem_u32(const void* p) {
    uint32_t a;
    asm("{ .reg .u64 t; cvta.to.shared.u64 t, %1; cvt.u32.u64 %0, t; }" : "=r"(a) : "l"(p));
    return a;
}
#define SW128(o) ((o) ^ (((o) >> 3) & 0x70))
__device__ __forceinline__ uint32_t f2tf32(float f) {
    uint32_t r;
    asm("cvt.rna.tf32.f32 %0, %1;" : "=r"(r) : "f"(f));
    return r;
}

#if HAS_TC05
__device__ __forceinline__ uint32_t elect_one() {
    uint32_t p;
    asm volatile("{ .reg .pred p; elect.sync _|p, 0xFFFFFFFF; selp.b32 %0, 1, 0, p; }" : "=r"(p));
    return p;
}
__device__ __forceinline__ uint64_t make_desc(uint32_t addr) {
    // SW128, version=1(Blackwell), SBO=64, LBO=1  (K-major, 128B rows)
    const uint64_t base = (uint64_t(2) << 61) | (uint64_t(1) << 46)
                        | (uint64_t(64) << 32) | (uint64_t(1) << 16);
    return base | ((uint64_t)(addr >> 4) & 0x3FFF);
}
__device__ __forceinline__ void mma_tf32_ss(uint32_t d, uint64_t ad, uint64_t bd,
                                            uint32_t idesc, uint32_t en) {
    asm volatile(
        "{\n\t.reg .pred p;\n\tsetp.ne.u32 p, %5, 0;\n\t"
        "tcgen05.mma.cta_group::1.kind::tf32 [%0], %1, %2, %3, {%4, %4, %4, %4}, p;\n\t}"
        :: "r"(d), "l"(ad), "l"(bd), "r"(idesc), "r"(0u), "r"(en) : "memory");
}
__device__ __forceinline__ void mbar_init(uint32_t a, uint32_t cnt) {
    asm volatile("mbarrier.init.shared.b64 [%0], %1;" :: "r"(a), "r"(cnt) : "memory");
}
__device__ __forceinline__ void mbar_inval(uint32_t a) {
    asm volatile("mbarrier.inval.shared.b64 [%0];" :: "r"(a) : "memory");
}
__device__ __forceinline__ void mbar_wait(uint32_t a, uint32_t parity) {
    asm volatile(
        "{\n\t.reg .pred P;\n"
        "W_%=:\n\t"
        "mbarrier.try_wait.parity.acquire.cta.shared::cta.b64 P, [%0], %1, 0x989680;\n\t"
        "@P bra D_%=;\n\tbra W_%=;\nD_%=:\n\t}"
        :: "r"(a), "r"(parity) : "memory");
}
__device__ __forceinline__ void mbar_expect_tx(uint32_t a, uint32_t bytes) {
    asm volatile("mbarrier.arrive.expect_tx.shared.b64 _, [%0], %1;"
                 :: "r"(a), "r"(bytes) : "memory");
}
__device__ __forceinline__ void bulk_g2s(uint32_t dst, const void* src,
                                         uint32_t bytes, uint32_t mbar) {
    asm volatile(
        "cp.async.bulk.shared::cta.global.mbarrier::complete_tx::bytes [%0], [%1], %2, [%3];"
        :: "r"(dst), "l"(src), "r"(bytes), "r"(mbar) : "memory");
}
__device__ __forceinline__ void tmem_commit(uint32_t mbar) {
    asm volatile(
        "tcgen05.commit.cta_group::1.mbarrier::arrive::one.shared::cluster.b64 [%0];"
        :: "r"(mbar) : "memory");
}
#define TC_ALLOC(dst, n)   asm volatile("tcgen05.alloc.cta_group::1.sync.aligned.shared::cta.b32 [%0], %1;" :: "r"(dst), "r"(n) : "memory")
#define TC_DEALLOC(t, n)   asm volatile("tcgen05.dealloc.cta_group::1.sync.aligned.b32 %0, %1;" :: "r"(t), "r"(n))
#define TC_RELINQ()        asm volatile("tcgen05.relinquish_alloc_permit.cta_group::1.sync.aligned;")
#define TC_FENCE_AFTER()   asm volatile("tcgen05.fence::after_thread_sync;" ::: "memory")
#define TC_FENCE_BEFORE()  asm volatile("tcgen05.fence::before_thread_sync;" ::: "memory")
#define TC_WAIT_LD()       asm volatile("tcgen05.wait::ld.sync.aligned;" ::: "memory")
#define FENCE_ASYNC()      asm volatile("fence.proxy.async.shared::cta;" ::: "memory")

#define LD_X32(r, a) \
    asm volatile("tcgen05.ld.sync.aligned.32x32b.x32.b32 " \
        "{%0,%1,%2,%3,%4,%5,%6,%7,%8,%9,%10,%11,%12,%13,%14,%15," \
        "%16,%17,%18,%19,%20,%21,%22,%23,%24,%25,%26,%27,%28,%29,%30,%31}, [%32];" \
        : "=r"((r)[0]),"=r"((r)[1]),"=r"((r)[2]),"=r"((r)[3]), \
          "=r"((r)[4]),"=r"((r)[5]),"=r"((r)[6]),"=r"((r)[7]), \
          "=r"((r)[8]),"=r"((r)[9]),"=r"((r)[10]),"=r"((r)[11]), \
          "=r"((r)[12]),"=r"((r)[13]),"=r"((r)[14]),"=r"((r)[15]), \
          "=r"((r)[16]),"=r"((r)[17]),"=r"((r)[18]),"=r"((r)[19]), \
          "=r"((r)[20]),"=r"((r)[21]),"=r"((r)[22]),"=r"((r)[23]), \
          "=r"((r)[24]),"=r"((r)[25]),"=r"((r)[26]),"=r"((r)[27]), \
          "=r"((r)[28]),"=r"((r)[29]),"=r"((r)[30]),"=r"((r)[31]) \
        : "r"(a))
#endif  // HAS_TC05

// ---------------------------------------------------------------------------
__global__ void k_softmax(const float* __restrict__ alphas) {
    int e = threadIdx.x;
    if (e < 8) {
        float m = -1e30f;
        #pragma unroll
        for (int i = 0; i < 5; i++) m = fmaxf(m, alphas[e*5+i]);
        float ex[5]; float s = 0.f;
        #pragma unroll
        for (int i = 0; i < 5; i++) { ex[i] = expf(alphas[e*5+i] - m); s += ex[i]; }
        float inv = 1.f / s;
        #pragma unroll
        for (int i = 0; i < 5; i++) g_asoft[e*5+i] = ex[i] * inv;
    }
}

__global__ void k_kdec() {
    int kp = blockIdx.x * 256 + threadIdx.x;
    if (kp >= KEDGE) return;
    int ci = kp / 18, t = kp - ci*18;
    int dy, dx;
    if (t < 9) { dy = t/3 - 1; dx = t%3 - 1; }
    else { int u = t - 9; dy = (u/3)*2 - 2; dx = (u%3)*2 - 2; }
    g_kdec[kp] = ci | ((dy+2) << 8) | ((dx+2) << 12);
}

__global__ void k_combine_tiles(const float* __restrict__ w3, const float* __restrict__ wd3) {
    int idx = blockIdx.x * 256 + threadIdx.x;     // < 8*72*128*32
    int kk = idx & 31;
    int r  = idx >> 5;
    int co = r & 127;
    int et = r >> 7;                               // e*72 + tile
    int e  = et / 72, tl = et - e*72;
    int kp = tl*32 + kk;
    int ci = kp / 18, t = kp - ci*18;
    float a = (t < 9) ? g_asoft[e*5+1] : g_asoft[e*5+2];
    int tt  = (t < 9) ? t : t - 9;
    float val = a * ((t < 9 ? w3 : wd3)[((e*C + co)*C + ci)*9 + tt]);
    uint32_t off = SW128((uint32_t)(co*128 + kk*4));
    *(uint32_t*)((char*)gA + (size_t)et*TILE_BYTES + off) = f2tf32(val);
}

// ---------------------------------------------------------------------------
__global__ __launch_bounds__(256) void k_pre(const float* __restrict__ in,
                                             const float* __restrict__ w,
                                             float* __restrict__ out) {
    __shared__ __align__(16) float tin[8][HW];
    __shared__ float tw[8][16];
    int b   = blockIdx.x >> 3;
    int co0 = (blockIdx.x & 7) << 4;
    int tid = threadIdx.x;
    int px0 = tid * 4;
    const float* inb = in + b*C*HW;
    float acc[16][4] = {};
    for (int cic = 0; cic < C; cic += 8) {
        __syncthreads();
        #pragma unroll
        for (int k = 0; k < 8; k++) {
            int f = tid + k*256;
            ((float4*)tin)[f] = ((const float4*)(inb + cic*HW))[f];
        }
        if (tid < 128) {
            int ci = tid >> 4, co = tid & 15;
            tw[ci][co] = w[(co0+co)*C + cic + ci];
        }
        __syncthreads();
        #pragma unroll
        for (int ci = 0; ci < 8; ci++) {
            float4 i4 = *(const float4*)&tin[ci][px0];
            float iv[4] = {i4.x, i4.y, i4.z, i4.w};
            #pragma unroll
            for (int co = 0; co < 16; co++) {
                float wv = tw[ci][co];
                #pragma unroll
                for (int j = 0; j < 4; j++) acc[co][j] += wv * iv[j];
            }
        }
    }
    float* ob = out + (b*C + co0)*HW + px0;
    #pragma unroll
    for (int co = 0; co < 16; co++)
        *(float4*)(ob + co*HW) = make_float4(acc[co][0], acc[co][1], acc[co][2], acc[co][3]);
}

// ---------------------------------------------------------------------------
// tcgen05 tf32 implicit-GEMM node kernel, N=256 per CTA.
// block = (b, 256-px chunk).  D[co=128][px=256] in TMEM (256 cols),
// K = 144 tiles of 32.  A via cp.async.bulk; B im2col by threads.
// ---------------------------------------------------------------------------
__global__ __launch_bounds__(256) void k_node_mma(
    const float* __restrict__ h0, int h0bs,
    const float* __restrict__ h1, int h1bs,
    float* __restrict__ outR, int eA, int eB)
{
#if HAS_TC05
    extern __shared__ char dsm_raw[];
    char* dsm = (char*)(((uintptr_t)dsm_raw + 1023) & ~(uintptr_t)1023);
    // per buffer: A @ +0 (16KB), B @ +16K (32KB); buffers at 0, 49152
    __shared__ __align__(16) uint64_t mbar[2];   // MMA-done per buffer
    __shared__ __align__(16) uint64_t abar[2];   // A-tile-arrived per buffer
    __shared__ uint32_t tmem_ptr_s;

    const int tid = threadIdx.x;
    const int wid = tid >> 5;
    const int b   = blockIdx.x >> 2;
    const int pc  = blockIdx.x & 3;

    if (wid == 0) {
        TC_ALLOC(smem_u32(&tmem_ptr_s), 256);
        TC_RELINQ();
    }
    if (tid == 0) {
        mbar_init(smem_u32(&mbar[0]), 1);
        mbar_init(smem_u32(&mbar[1]), 1);
        mbar_init(smem_u32(&abar[0]), 1);
        mbar_init(smem_u32(&abar[1]), 1);
    }
    __syncthreads();
    const uint32_t tmem = tmem_ptr_s;
    const uint32_t mb0 = smem_u32(&mbar[0]);
    const uint32_t mb1 = smem_u32(&mbar[1]);
    const uint32_t ab0 = smem_u32(&abar[0]);
    const uint32_t ab1 = smem_u32(&abar[1]);

    const bool leader = (wid == 0) && elect_one();

    const int px    = tid;                 // 0..255
    const int ybase = pc*8 + (px >> 5);    // 0..31
    const int x     = px & 31;
    const float* hA = h0 + (long long)b * h0bs;
    const float* hB = h1 + (long long)b * h1bs;

    int ph0 = 0, ph1 = 0;      // MMA-done phases
    int aph0 = 0, aph1 = 0;    // A-arrival phases

    for (int t = 0; t < NTILES; t++) {
        const int buf = t & 1;
        const uint32_t mb = buf ? mb1 : mb0;
        const uint32_t ab = buf ? ab1 : ab0;
        if (t >= 2) {
            if (buf) { mbar_wait(mb1, ph1); ph1 ^= 1; }
            else     { mbar_wait(mb0, ph0); ph0 ^= 1; }
        }
        const int e  = (t < NTILE_EDGE) ? eA : eB;
        const int te = (t < NTILE_EDGE) ? t : t - NTILE_EDGE;
        // ---- A tile: async bulk copy of pre-swizzled tf32 tile ----
        if (leader) {
            mbar_expect_tx(ab, TILE_BYTES);
            bulk_g2s(smem_u32(dsm + buf*BUF_STRIDE),
                     (const char*)gA + (size_t)(e*NTILE_EDGE + te)*TILE_BYTES,
                     TILE_BYTES, ab);
        }
        // ---- B tile im2col build: each thread builds its px row (32 k) ----
        {
            const float* hb = (t < NTILE_EDGE) ? hA : hB;
            char* Bd = dsm + buf*BUF_STRIDE + TILE_BYTES;
            const int kbase = te * 32;
            #pragma unroll
            for (int g = 0; g < 8; g++) {
                uint32_t v[4];
                #pragma unroll
                for (int q = 0; q < 4; q++) {
                    int dec = g_kdec[kbase + g*4 + q];
                    int ci = dec & 255;
                    int yy = ybase + ((dec >> 8) & 15) - 2;
                    int xx = x + ((dec >> 12) & 15) - 2;
                    float f = 0.f;
                    if ((unsigned)yy < 32u && (unsigned)xx < 32u)
                        f = __ldg(&hb[ci*HW + yy*32 + xx]);
                    v[q] = f2tf32(f);
                }
                uint32_t off = SW128((uint32_t)(px*128 + g*16));
                *(uint4*)(Bd + off) = make_uint4(v[0], v[1], v[2], v[3]);
            }
        }
        __syncthreads();
        if (leader) {
            FENCE_ASYNC();
            if (buf) { mbar_wait(ab1, aph1); aph1 ^= 1; }
            else     { mbar_wait(ab0, aph0); aph0 ^= 1; }
            uint64_t ad = make_desc(smem_u32(dsm + buf*BUF_STRIDE));
            uint64_t bd = make_desc(smem_u32(dsm + buf*BUF_STRIDE + TILE_BYTES));
            #pragma unroll
            for (int k = 0; k < 4; k++)
                mma_tf32_ss(tmem, ad + k*2, bd + k*2, IDESC_TF32_N256,
                            (t == 0 && k == 0) ? 0u : 1u);
            tmem_commit(mb);
        }
    }
    mbar_wait(mb1, ph1);
    TC_FENCE_AFTER();

    // ---- epilogue: 8 warps x 4 x32-loads cover 128co x 256px ----
    {
        const int lg      = wid & 3;                   // lane group (co/32)
        const uint32_t woff = ((uint32_t)lg) << 21;
        const int co      = lg*32 + (tid & 31);
        const int colbase = (wid >> 2) * 128;          // 0 or 128
        float* op = outR + (long long)b*OUT_BSTRIDE + co*HW + pc*256 + colbase;
        #pragma unroll
        for (int c = 0; c < 4; c++) {
            uint32_t r[32];
            LD_X32(r, tmem + colbase + c*32 + woff);
            TC_WAIT_LD();
            #pragma unroll
            for (int j = 0; j < 8; j++)
                ((float4*)(op + c*32))[j] = make_float4(
                    __uint_as_float(r[j*4+0]), __uint_as_float(r[j*4+1]),
                    __uint_as_float(r[j*4+2]), __uint_as_float(r[j*4+3]));
        }
        TC_FENCE_BEFORE();
    }
    __syncthreads();
    if (tid == 0) { mbar_inval(mb0); mbar_inval(mb1); mbar_inval(ab0); mbar_inval(ab1); }
    __syncthreads();
    if (wid == 0) TC_DEALLOC(tmem, 256);
#endif  // HAS_TC05
}

// ---------------------------------------------------------------------------
// identity + avg3 + max3 terms (exact fp32), RMW into out region.
// ---------------------------------------------------------------------------
__global__ __launch_bounds__(256) void k_pool(
    const float* __restrict__ h0, int h0bs,
    const float* __restrict__ h1, int h1bs,
    float* __restrict__ outR, int eA, int eB)
{
    __shared__ float tl[8][34*36];
    const int b  = blockIdx.x >> 5;
    const int c0 = (blockIdx.x & 31) << 2;
    const int tid = threadIdx.x;

    for (int i = tid; i < 8*34*36; i += 256) ((float*)tl)[i] = 0.f;
    __syncthreads();
    for (int i = tid; i < 8*HW; i += 256) {
        int e = i >> 12, ch = (i >> 10) & 3, p = i & 1023;
        int y = p >> 5, xx = p & 31;
        const float* hb = e ? (h1 + (long long)b*h1bs) : (h0 + (long long)b*h0bs);
        tl[e*4+ch][(y+1)*36 + xx + 1] = hb[(c0+ch)*HW + p];
    }
    __syncthreads();

    float a0[2], a3[2], a4[2];
    a0[0] = g_asoft[eA*5+0]; a3[0] = g_asoft[eA*5+3]*(1.f/9.f); a4[0] = g_asoft[eA*5+4];
    a0[1] = g_asoft[eB*5+0]; a3[1] = g_asoft[eB*5+3]*(1.f/9.f); a4[1] = g_asoft[eB*5+4];

    const int ch = tid >> 6;
    float* op = outR + (long long)b*OUT_BSTRIDE + (c0+ch)*HW;
    #pragma unroll 4
    for (int j = 0; j < 16; j++) {
        int p = (tid & 63) + j*64;
        int y = p >> 5, xx = p & 31;
        int base = (y+1)*36 + xx + 1;
        float acc = 0.f;
        #pragma unroll
        for (int e = 0; e < 2; e++) {
            const float* tc = tl[e*4+ch];
            float cv = tc[base];
            float sum = 0.f, mx = -INFINITY;
            #pragma unroll
            for (int dy = -1; dy <= 1; dy++)
                #pragma unroll
                for (int dx = -1; dx <= 1; dx++) {
                    float v = tc[base + dy*36 + dx];
                    sum += v;
                    bool ok = ((unsigned)(y+dy) < 32u) && ((unsigned)(xx+dx) < 32u);
                    if (ok) mx = fmaxf(mx, v);
                }
            acc += a0[e]*cv + a3[e]*sum + a4[e]*mx;
        }
        op[p] += acc;
    }
}

// ---------------------------------------------------------------------------
__global__ void k_copy_skip(const float* __restrict__ skip,
                            float* __restrict__ out,
                            float* __restrict__ out2) {
    int i = blockIdx.x * 256 + threadIdx.x;
    if (i >= (BATCH*C*HW)/4) return;
    float4 v = ((const float4*)skip)[i];
    int pe = i * 4;
    int b  = pe >> 17;
    int r  = pe & (C*HW - 1);
    *(float4*)(out + (long long)b*OUT_BSTRIDE + 4*C*HW + r) = v;
    if (out2) ((float4*)out2)[i] = v;
}

// ---------------------------------------------------------------------------
static void launch_node(const float* h0, int h0bs, const float* h1, int h1bs,
                        float* outR, int eA, int eB, int dsmem) {
    k_node_mma<<<BATCH*4, 256, dsmem>>>(h0, h0bs, h1, h1bs, outR, eA, eB);
    k_pool    <<<BATCH*32, 256>>>      (h0, h0bs, h1, h1bs, outR, eA, eB);
}

extern "C" void kernel_launch(void* const* d_in, const int* in_sizes, int n_in,
                              void* d_out, int out_size) {
    const float* input0 = (const float*)d_in[0];
    const float* input1 = (const float*)d_in[1];
    const float* skip   = (const float*)d_in[2];
    const float* w_pre0 = (const float*)d_in[3];
    const float* w_pre1 = (const float*)d_in[4];
    const float* w3     = (const float*)d_in[5];
    const float* wd3    = (const float*)d_in[6];
    const float* alphas = (const float*)d_in[7];
    float* out = (float*)d_out;

    float *s0, *s1;
    cudaGetSymbolAddress((void**)&s0, g_s0);
    cudaGetSymbolAddress((void**)&s1, g_s1);

    const int DSMEM = 2*BUF_STRIDE + 1024;   // 99328
    cudaFuncSetAttribute(k_node_mma, cudaFuncAttributeMaxDynamicSharedMemorySize, DSMEM);

    k_softmax<<<1, 8>>>(alphas);
    k_kdec<<<(KEDGE + 255)/256, 256>>>();
    k_combine_tiles<<<(8*NTILE_EDGE*TILE_FLOATS)/256, 256>>>(w3, wd3);
    k_pre<<<BATCH*8, 256>>>(input0, w_pre0, s0);
    k_pre<<<BATCH*8, 256>>>(input1, w_pre1, s1);

    launch_node(s0, REG_STRIDE, s1, REG_STRIDE,                         out + 0*C*HW, 0, 1, DSMEM);
    launch_node(s1, REG_STRIDE, out + 0*C*HW, OUT_BSTRIDE,              out + 1*C*HW, 2, 3, DSMEM);
    launch_node(out + 0*C*HW, OUT_BSTRIDE, out + 1*C*HW, OUT_BSTRIDE,   out + 2*C*HW, 4, 5, DSMEM);
    launch_node(out + 1*C*HW, OUT_BSTRIDE, out + 2*C*HW, OUT_BSTRIDE,   out + 3*C*HW, 6, 7, DSMEM);

    long long concat_elems = (long long)BATCH*OUTC*HW;
    long long skip_elems   = (long long)BATCH*C*HW;
    float* out2 = nullptr;
    if ((long long)out_size >= concat_elems + skip_elems)
        out2 = out + concat_elems;
    k_copy_skip<<<((BATCH*C*HW/4) + 255)/256, 256>>>(skip, out, out2);
}

// round 6
// speedup vs baseline: 5.1106x; 1.2834x over previous
#include <cuda_runtime.h>
#include <math.h>
#include <stdint.h>

#define BATCH 64
#define C 128
#define HW 1024
#define OUTC 640
#define REG_STRIDE (C*HW)
#define OUT_BSTRIDE (OUTC*HW)

#define KEDGE 2304            // 128 ci * 18 taps
#define NTILE_EDGE 72         // 2304 / 32
#define NTILES 144            // 2 edges
#define TILE_FLOATS 4096      // 128 rows * 32 k (A tile)
#define TILE_BYTES 16384      // A tile bytes
#define BTILE_BYTES 32768     // B tile: 256 px rows * 128B
#define BUF_STRIDE (TILE_BYTES + BTILE_BYTES)   // 49152
#define PLANE 432             // staged plane: 12 rows * 36 cols
#define STAGE_FLOATS (3*PLANE)   // 1296
#define STAGE_BYTES (STAGE_FLOATS*4)

// idesc kind::tf32: dtype=F32(bit4), atype=TF32=2, btype=TF32=2, N=256, M=128
#define IDESC_TF32_N256 ((1u<<4)|(2u<<7)|(2u<<10)|(32u<<17)|(8u<<24))

#if defined(__CUDA_ARCH_FEAT_SM103_ALL) || defined(__CUDA_ARCH_FEAT_SM100_ALL) || \
    (defined(__CUDA_ARCH_SPECIFIC__) && (__CUDA_ARCH_SPECIFIC__ >= 1000))
#define HAS_TC05 1
#else
#define HAS_TC05 0
#endif

__device__ float g_s0[BATCH*C*HW];
__device__ float g_s1[BATCH*C*HW];
__device__ __align__(16) uint32_t gA[8*NTILE_EDGE*TILE_FLOATS];  // tf32 bits, swizzled A-tiles
__device__ int   g_kdec[KEDGE];    // precombined smem offset: ci_rel*432 + (dy+2)*36 + (dx+2)
__device__ float g_asoft[8*5];

// ---------------------------------------------------------------------------
__device__ __forceinline__ uint32_t smem_u32(const void* p) {
    uint32_t a;
    asm("{ .reg .u64 t; cvta.to.shared.u64 t, %1; cvt.u32.u64 %0, t; }" : "=r"(a) : "l"(p));
    return a;
}
#define SW128(o) ((o) ^ (((o) >> 3) & 0x70))
__device__ __forceinline__ uint32_t f2tf32(float f) {
    uint32_t r;
    asm("cvt.rna.tf32.f32 %0, %1;" : "=r"(r) : "f"(f));
    return r;
}

#if HAS_TC05
__device__ __forceinline__ uint32_t elect_one() {
    uint32_t p;
    asm volatile("{ .reg .pred p; elect.sync _|p, 0xFFFFFFFF; selp.b32 %0, 1, 0, p; }" : "=r"(p));
    return p;
}
__device__ __forceinline__ uint64_t make_desc(uint32_t addr) {
    // SW128, version=1(Blackwell), SBO=64, LBO=1  (K-major, 128B rows)
    const uint64_t base = (uint64_t(2) << 61) | (uint64_t(1) << 46)
                        | (uint64_t(64) << 32) | (uint64_t(1) << 16);
    return base | ((uint64_t)(addr >> 4) & 0x3FFF);
}
__device__ __forceinline__ void mma_tf32_ss(uint32_t d, uint64_t ad, uint64_t bd,
                                            uint32_t idesc, uint32_t en) {
    asm volatile(
        "{\n\t.reg .pred p;\n\tsetp.ne.u32 p, %5, 0;\n\t"
        "tcgen05.mma.cta_group::1.kind::tf32 [%0], %1, %2, %3, {%4, %4, %4, %4}, p;\n\t}"
        :: "r"(d), "l"(ad), "l"(bd), "r"(idesc), "r"(0u), "r"(en) : "memory");
}
__device__ __forceinline__ void mbar_init(uint32_t a, uint32_t cnt) {
    asm volatile("mbarrier.init.shared.b64 [%0], %1;" :: "r"(a), "r"(cnt) : "memory");
}
__device__ __forceinline__ void mbar_inval(uint32_t a) {
    asm volatile("mbarrier.inval.shared.b64 [%0];" :: "r"(a) : "memory");
}
__device__ __forceinline__ void mbar_wait(uint32_t a, uint32_t parity) {
    asm volatile(
        "{\n\t.reg .pred P;\n"
        "W_%=:\n\t"
        "mbarrier.try_wait.parity.acquire.cta.shared::cta.b64 P, [%0], %1, 0x989680;\n\t"
        "@P bra D_%=;\n\tbra W_%=;\nD_%=:\n\t}"
        :: "r"(a), "r"(parity) : "memory");
}
__device__ __forceinline__ void mbar_expect_tx(uint32_t a, uint32_t bytes) {
    asm volatile("mbarrier.arrive.expect_tx.shared.b64 _, [%0], %1;"
                 :: "r"(a), "r"(bytes) : "memory");
}
__device__ __forceinline__ void bulk_g2s(uint32_t dst, const void* src,
                                         uint32_t bytes, uint32_t mbar) {
    asm volatile(
        "cp.async.bulk.shared::cta.global.mbarrier::complete_tx::bytes [%0], [%1], %2, [%3];"
        :: "r"(dst), "l"(src), "r"(bytes), "r"(mbar) : "memory");
}
__device__ __forceinline__ void tmem_commit(uint32_t mbar) {
    asm volatile(
        "tcgen05.commit.cta_group::1.mbarrier::arrive::one.shared::cluster.b64 [%0];"
        :: "r"(mbar) : "memory");
}
#define TC_ALLOC(dst, n)   asm volatile("tcgen05.alloc.cta_group::1.sync.aligned.shared::cta.b32 [%0], %1;" :: "r"(dst), "r"(n) : "memory")
#define TC_DEALLOC(t, n)   asm volatile("tcgen05.dealloc.cta_group::1.sync.aligned.b32 %0, %1;" :: "r"(t), "r"(n))
#define TC_RELINQ()        asm volatile("tcgen05.relinquish_alloc_permit.cta_group::1.sync.aligned;")
#define TC_FENCE_AFTER()   asm volatile("tcgen05.fence::after_thread_sync;" ::: "memory")
#define TC_FENCE_BEFORE()  asm volatile("tcgen05.fence::before_thread_sync;" ::: "memory")
#define TC_WAIT_LD()       asm volatile("tcgen05.wait::ld.sync.aligned;" ::: "memory")
#define FENCE_ASYNC()      asm volatile("fence.proxy.async.shared::cta;" ::: "memory")

#define LD_X32(r, a) \
    asm volatile("tcgen05.ld.sync.aligned.32x32b.x32.b32 " \
        "{%0,%1,%2,%3,%4,%5,%6,%7,%8,%9,%10,%11,%12,%13,%14,%15," \
        "%16,%17,%18,%19,%20,%21,%22,%23,%24,%25,%26,%27,%28,%29,%30,%31}, [%32];" \
        : "=r"((r)[0]),"=r"((r)[1]),"=r"((r)[2]),"=r"((r)[3]), \
          "=r"((r)[4]),"=r"((r)[5]),"=r"((r)[6]),"=r"((r)[7]), \
          "=r"((r)[8]),"=r"((r)[9]),"=r"((r)[10]),"=r"((r)[11]), \
          "=r"((r)[12]),"=r"((r)[13]),"=r"((r)[14]),"=r"((r)[15]), \
          "=r"((r)[16]),"=r"((r)[17]),"=r"((r)[18]),"=r"((r)[19]), \
          "=r"((r)[20]),"=r"((r)[21]),"=r"((r)[22]),"=r"((r)[23]), \
          "=r"((r)[24]),"=r"((r)[25]),"=r"((r)[26]),"=r"((r)[27]), \
          "=r"((r)[28]),"=r"((r)[29]),"=r"((r)[30]),"=r"((r)[31]) \
        : "r"(a))
#endif  // HAS_TC05

// ---------------------------------------------------------------------------
__global__ void k_softmax(const float* __restrict__ alphas) {
    int e = threadIdx.x;
    if (e < 8) {
        float m = -1e30f;
        #pragma unroll
        for (int i = 0; i < 5; i++) m = fmaxf(m, alphas[e*5+i]);
        float ex[5]; float s = 0.f;
        #pragma unroll
        for (int i = 0; i < 5; i++) { ex[i] = expf(alphas[e*5+i] - m); s += ex[i]; }
        float inv = 1.f / s;
        #pragma unroll
        for (int i = 0; i < 5; i++) g_asoft[e*5+i] = ex[i] * inv;
    }
}

// kdec: precombined smem plane offset per k': ci_rel*PLANE + (dy+2)*36 + (dx+2)
__global__ void k_kdec() {
    int kp = blockIdx.x * 256 + threadIdx.x;
    if (kp >= KEDGE) return;
    int ci = kp / 18, t = kp - ci*18;
    int dy, dx;
    if (t < 9) { dy = t/3 - 1; dx = t%3 - 1; }
    else { int u = t - 9; dy = (u/3)*2 - 2; dx = (u%3)*2 - 2; }
    int tile = kp >> 5;
    int ci0 = (tile*32) / 18;
    g_kdec[kp] = (ci - ci0)*PLANE + (dy+2)*36 + (dx+2);
}

// Build gA: alpha-folded conv weights + linear pool terms, swizzled tf32 tiles.
// identity (a0) and avg-pool (a3/9) are linear => folded into dil-1 taps at ci==co.
__global__ void k_combine_tiles(const float* __restrict__ w3, const float* __restrict__ wd3) {
    int idx = blockIdx.x * 256 + threadIdx.x;     // < 8*72*128*32
    int kk = idx & 31;
    int r  = idx >> 5;
    int co = r & 127;
    int et = r >> 7;                               // e*72 + tile
    int e  = et / 72, tl = et - e*72;
    int kp = tl*32 + kk;
    int ci = kp / 18, t = kp - ci*18;
    float a = (t < 9) ? g_asoft[e*5+1] : g_asoft[e*5+2];
    int tt  = (t < 9) ? t : t - 9;
    float val = a * ((t < 9 ? w3 : wd3)[((e*C + co)*C + ci)*9 + tt]);
    if (co == ci && t < 9) {
        val += g_asoft[e*5+3] * (1.f/9.f);        // avg-pool (count_include_pad)
        if (t == 4) val += g_asoft[e*5+0];        // identity (center tap)
    }
    uint32_t off = SW128((uint32_t)(co*128 + kk*4));
    *(uint32_t*)((char*)gA + (size_t)et*TILE_BYTES + off) = f2tf32(val);
}

// ---------------------------------------------------------------------------
__global__ __launch_bounds__(256) void k_pre(const float* __restrict__ in,
                                             const float* __restrict__ w,
                                             float* __restrict__ out) {
    __shared__ __align__(16) float tin[8][HW];
    __shared__ float tw[8][16];
    int b   = blockIdx.x >> 3;
    int co0 = (blockIdx.x & 7) << 4;
    int tid = threadIdx.x;
    int px0 = tid * 4;
    const float* inb = in + b*C*HW;
    float acc[16][4] = {};
    for (int cic = 0; cic < C; cic += 8) {
        __syncthreads();
        #pragma unroll
        for (int k = 0; k < 8; k++) {
            int f = tid + k*256;
            ((float4*)tin)[f] = ((const float4*)(inb + cic*HW))[f];
        }
        if (tid < 128) {
            int ci = tid >> 4, co = tid & 15;
            tw[ci][co] = w[(co0+co)*C + cic + ci];
        }
        __syncthreads();
        #pragma unroll
        for (int ci = 0; ci < 8; ci++) {
            float4 i4 = *(const float4*)&tin[ci][px0];
            float iv[4] = {i4.x, i4.y, i4.z, i4.w};
            #pragma unroll
            for (int co = 0; co < 16; co++) {
                float wv = tw[ci][co];
                #pragma unroll
                for (int j = 0; j < 4; j++) acc[co][j] += wv * iv[j];
            }
        }
    }
    float* ob = out + (b*C + co0)*HW + px0;
    #pragma unroll
    for (int co = 0; co < 16; co++)
        *(float4*)(ob + co*HW) = make_float4(acc[co][0], acc[co][1], acc[co][2], acc[co][3]);
}

// ---------------------------------------------------------------------------
// tcgen05 tf32 implicit-GEMM node kernel, N=256 per CTA, smem-staged im2col.
// block = (b, 256-px chunk) = 8 rows x 32 cols.  D[128co][256px] in TMEM.
// Per K-tile (32 k), the <=3 needed ci planes (12x36, zero halo) are staged
// into smem one iteration ahead; B rows built via LDS (no predicates).
// ---------------------------------------------------------------------------
__global__ __launch_bounds__(256) void k_node_mma(
    const float* __restrict__ h0, int h0bs,
    const float* __restrict__ h1, int h1bs,
    float* __restrict__ outR, int eA, int eB)
{
#if HAS_TC05
    extern __shared__ char dsm_raw[];
    char* dsm = (char*)(((uintptr_t)dsm_raw + 1023) & ~(uintptr_t)1023);
    // layout: [A0 16K | B0 32K | A1 16K | B1 32K | stage0 5184B | stage1 5184B]
    float* stageF = (float*)(dsm + 2*BUF_STRIDE);
    __shared__ __align__(16) uint64_t mbar[2];   // MMA-done per buffer
    __shared__ __align__(16) uint64_t abar[2];   // A-tile-arrived per buffer
    __shared__ uint32_t tmem_ptr_s;

    const int tid = threadIdx.x;
    const int wid = tid >> 5;
    const int b   = blockIdx.x >> 2;
    const int pc  = blockIdx.x & 3;

    if (wid == 0) {
        TC_ALLOC(smem_u32(&tmem_ptr_s), 256);
        TC_RELINQ();
    }
    if (tid == 0) {
        mbar_init(smem_u32(&mbar[0]), 1);
        mbar_init(smem_u32(&mbar[1]), 1);
        mbar_init(smem_u32(&abar[0]), 1);
        mbar_init(smem_u32(&abar[1]), 1);
    }
    __syncthreads();
    const uint32_t tmem = tmem_ptr_s;
    const uint32_t mb0 = smem_u32(&mbar[0]);
    const uint32_t mb1 = smem_u32(&mbar[1]);
    const uint32_t ab0 = smem_u32(&abar[0]);
    const uint32_t ab1 = smem_u32(&abar[1]);

    const bool leader = (wid == 0) && elect_one();

    const int px    = tid;                 // 0..255
    const int y0    = pc*8;                // block's first row
    const int tbase = (px >> 5)*36 + (px & 31);   // thread offset within plane
    const float* hA = h0 + (long long)b * h0bs;
    const float* hB = h1 + (long long)b * h1bs;

    int ph0 = 0, ph1 = 0;      // MMA-done phases
    int aph0 = 0, aph1 = 0;    // A-arrival phases

    // ---- staging lambda (tile index tt in 0..143) ----
    auto stage = [&](int tt) {
        const float* img = (tt < NTILE_EDGE) ? hA : hB;
        const int te  = (tt < NTILE_EDGE) ? tt : tt - NTILE_EDGE;
        const int ci0 = (te*32) / 18;
        float* sp = stageF + (tt & 1)*STAGE_FLOATS;
        #pragma unroll
        for (int ii = 0; ii < 6; ii++) {
            int i = tid + ii*256;
            if (i < STAGE_FLOATS) {
                int p   = i / PLANE;
                int r   = i - p*PLANE;
                int row = r / 36, col = r - row*36;
                int ci  = ci0 + p; if (ci > 127) ci = 127;
                int gy  = y0 + row - 2;
                int gx  = col - 2;
                float v = 0.f;
                if ((unsigned)gy < 32u && (unsigned)gx < 32u)
                    v = __ldg(&img[ci*HW + gy*32 + gx]);
                sp[i] = v;
            }
        }
    };

    stage(0);
    __syncthreads();

    for (int t = 0; t < NTILES; t++) {
        const int buf = t & 1;
        const uint32_t mb = buf ? mb1 : mb0;
        const uint32_t ab = buf ? ab1 : ab0;
        if (t >= 2) {
            if (buf) { mbar_wait(mb1, ph1); ph1 ^= 1; }
            else     { mbar_wait(mb0, ph0); ph0 ^= 1; }
        }
        const int e  = (t < NTILE_EDGE) ? eA : eB;
        const int te = (t < NTILE_EDGE) ? t : t - NTILE_EDGE;
        // ---- A tile: async bulk copy of pre-swizzled tf32 tile ----
        if (leader) {
            mbar_expect_tx(ab, TILE_BYTES);
            bulk_g2s(smem_u32(dsm + buf*BUF_STRIDE),
                     (const char*)gA + (size_t)(e*NTILE_EDGE + te)*TILE_BYTES,
                     TILE_BYTES, ab);
        }
        // ---- B tile build from staged planes (LDS only) ----
        {
            const float* sp = stageF + buf*STAGE_FLOATS;
            char* Bd = dsm + buf*BUF_STRIDE + TILE_BYTES;
            const int kbase = te * 32;
            #pragma unroll
            for (int g = 0; g < 8; g++) {
                uint32_t v[4];
                #pragma unroll
                for (int q = 0; q < 4; q++) {
                    int prec = g_kdec[kbase + g*4 + q];
                    v[q] = f2tf32(sp[prec + tbase]);
                }
                uint32_t off = SW128((uint32_t)(px*128 + g*16));
                *(uint4*)(Bd + off) = make_uint4(v[0], v[1], v[2], v[3]);
            }
        }
        // ---- stage planes for next tile (hidden behind this tile's MMA) ----
        if (t + 1 < NTILES) stage(t + 1);
        __syncthreads();
        if (leader) {
            FENCE_ASYNC();
            if (buf) { mbar_wait(ab1, aph1); aph1 ^= 1; }
            else     { mbar_wait(ab0, aph0); aph0 ^= 1; }
            uint64_t ad = make_desc(smem_u32(dsm + buf*BUF_STRIDE));
            uint64_t bd = make_desc(smem_u32(dsm + buf*BUF_STRIDE + TILE_BYTES));
            #pragma unroll
            for (int k = 0; k < 4; k++)
                mma_tf32_ss(tmem, ad + k*2, bd + k*2, IDESC_TF32_N256,
                            (t == 0 && k == 0) ? 0u : 1u);
            tmem_commit(mb);
        }
    }
    mbar_wait(mb1, ph1);
    TC_FENCE_AFTER();

    // ---- epilogue: 8 warps x 4 x32-loads cover 128co x 256px ----
    {
        const int lg      = wid & 3;                   // lane group (co/32)
        const uint32_t woff = ((uint32_t)lg) << 21;
        const int co      = lg*32 + (tid & 31);
        const int colbase = (wid >> 2) * 128;          // 0 or 128
        float* op = outR + (long long)b*OUT_BSTRIDE + co*HW + pc*256 + colbase;
        #pragma unroll
        for (int c = 0; c < 4; c++) {
            uint32_t r[32];
            LD_X32(r, tmem + colbase + c*32 + woff);
            TC_WAIT_LD();
            #pragma unroll
            for (int j = 0; j < 8; j++)
                ((float4*)(op + c*32))[j] = make_float4(
                    __uint_as_float(r[j*4+0]), __uint_as_float(r[j*4+1]),
                    __uint_as_float(r[j*4+2]), __uint_as_float(r[j*4+3]));
        }
        TC_FENCE_BEFORE();
    }
    __syncthreads();
    if (tid == 0) { mbar_inval(mb0); mbar_inval(mb1); mbar_inval(ab0); mbar_inval(ab1); }
    __syncthreads();
    if (wid == 0) TC_DEALLOC(tmem, 256);
#endif  // HAS_TC05
}

// ---------------------------------------------------------------------------
// max-pool term only (identity/avg folded into GEMM weights), RMW into out.
// ---------------------------------------------------------------------------
__global__ __launch_bounds__(256) void k_maxp(
    const float* __restrict__ h0, int h0bs,
    const float* __restrict__ h1, int h1bs,
    float* __restrict__ outR, int eA, int eB)
{
    __shared__ float tl[8][34*36];
    const int b  = blockIdx.x >> 5;
    const int c0 = (blockIdx.x & 31) << 2;
    const int tid = threadIdx.x;

    for (int i = tid; i < 8*34*36; i += 256) ((float*)tl)[i] = -INFINITY;
    __syncthreads();
    for (int i = tid; i < 8*HW; i += 256) {
        int e = i >> 12, ch = (i >> 10) & 3, p = i & 1023;
        int y = p >> 5, xx = p & 31;
        const float* hb = e ? (h1 + (long long)b*h1bs) : (h0 + (long long)b*h0bs);
        tl[e*4+ch][(y+1)*36 + xx + 1] = hb[(c0+ch)*HW + p];
    }
    __syncthreads();

    const float a4A = g_asoft[eA*5+4];
    const float a4B = g_asoft[eB*5+4];

    const int ch = tid >> 6;
    float* op = outR + (long long)b*OUT_BSTRIDE + (c0+ch)*HW;
    #pragma unroll 4
    for (int j = 0; j < 16; j++) {
        int p = (tid & 63) + j*64;
        int y = p >> 5, xx = p & 31;
        int base = (y+1)*36 + xx + 1;
        float acc = 0.f;
        #pragma unroll
        for (int e = 0; e < 2; e++) {
            const float* tc = tl[e*4+ch];
            float mx = -INFINITY;
            #pragma unroll
            for (int dy = -1; dy <= 1; dy++)
                #pragma unroll
                for (int dx = -1; dx <= 1; dx++)
                    mx = fmaxf(mx, tc[base + dy*36 + dx]);
            acc += (e ? a4B : a4A) * mx;
        }
        op[p] += acc;
    }
}

// ---------------------------------------------------------------------------
__global__ void k_copy_skip(const float* __restrict__ skip,
                            float* __restrict__ out,
                            float* __restrict__ out2) {
    int i = blockIdx.x * 256 + threadIdx.x;
    if (i >= (BATCH*C*HW)/4) return;
    float4 v = ((const float4*)skip)[i];
    int pe = i * 4;
    int b  = pe >> 17;
    int r  = pe & (C*HW - 1);
    *(float4*)(out + (long long)b*OUT_BSTRIDE + 4*C*HW + r) = v;
    if (out2) ((float4*)out2)[i] = v;
}

// ---------------------------------------------------------------------------
static void launch_node(const float* h0, int h0bs, const float* h1, int h1bs,
                        float* outR, int eA, int eB, int dsmem) {
    k_node_mma<<<BATCH*4, 256, dsmem>>>(h0, h0bs, h1, h1bs, outR, eA, eB);
    k_maxp    <<<BATCH*32, 256>>>      (h0, h0bs, h1, h1bs, outR, eA, eB);
}

extern "C" void kernel_launch(void* const* d_in, const int* in_sizes, int n_in,
                              void* d_out, int out_size) {
    const float* input0 = (const float*)d_in[0];
    const float* input1 = (const float*)d_in[1];
    const float* skip   = (const float*)d_in[2];
    const float* w_pre0 = (const float*)d_in[3];
    const float* w_pre1 = (const float*)d_in[4];
    const float* w3     = (const float*)d_in[5];
    const float* wd3    = (const float*)d_in[6];
    const float* alphas = (const float*)d_in[7];
    float* out = (float*)d_out;

    float *s0, *s1;
    cudaGetSymbolAddress((void**)&s0, g_s0);
    cudaGetSymbolAddress((void**)&s1, g_s1);

    const int DSMEM = 2*BUF_STRIDE + 2*STAGE_BYTES + 1024;   // 109696
    cudaFuncSetAttribute(k_node_mma, cudaFuncAttributeMaxDynamicSharedMemorySize, DSMEM);

    k_softmax<<<1, 8>>>(alphas);
    k_kdec<<<(KEDGE + 255)/256, 256>>>();
    k_combine_tiles<<<(8*NTILE_EDGE*TILE_FLOATS)/256, 256>>>(w3, wd3);
    k_pre<<<BATCH*8, 256>>>(input0, w_pre0, s0);
    k_pre<<<BATCH*8, 256>>>(input1, w_pre1, s1);

    launch_node(s0, REG_STRIDE, s1, REG_STRIDE,                         out + 0*C*HW, 0, 1, DSMEM);
    launch_node(s1, REG_STRIDE, out + 0*C*HW, OUT_BSTRIDE,              out + 1*C*HW, 2, 3, DSMEM);
    launch_node(out + 0*C*HW, OUT_BSTRIDE, out + 1*C*HW, OUT_BSTRIDE,   out + 2*C*HW, 4, 5, DSMEM);
    launch_node(out + 1*C*HW, OUT_BSTRIDE, out + 2*C*HW, OUT_BSTRIDE,   out + 3*C*HW, 6, 7, DSMEM);

    long long concat_elems = (long long)BATCH*OUTC*HW;
    long long skip_elems   = (long long)BATCH*C*HW;
    float* out2 = nullptr;
    if ((long long)out_size >= concat_elems + skip_elems)
        out2 = out + concat_elems;
    k_copy_skip<<<((BATCH*C*HW/4) + 255)/256, 256>>>(skip, out, out2);
}

// round 7
// speedup vs baseline: 7.2339x; 1.4155x over previous
#include <cuda_runtime.h>
#include <math.h>
#include <stdint.h>

#define BATCH 64
#define C 128
#define HW 1024
#define OUTC 640
#define REG_STRIDE (C*HW)
#define OUT_BSTRIDE (OUTC*HW)

#define KEDGE 2304            // 128 ci * 18 taps
#define NTILE_EDGE 72         // 2304 / 32
#define NTILES 144            // 2 edges
#define TILE_FLOATS 4096      // 128 rows * 32 k (A tile)
#define TILE_BYTES 16384      // A tile bytes
#define BTILE_BYTES 32768     // B tile: 256 px rows * 128B
#define BUF_STRIDE (TILE_BYTES + BTILE_BYTES)   // 49152
#define PLANE 432             // staged plane: 12 rows * 36 cols
#define STAGE_FLOATS (3*PLANE)   // 1296
#define STAGE_BYTES (STAGE_FLOATS*4)            // 5184
// smem layout offsets (relative to 1024-aligned dsm)
#define OFF_STAGE (2*BUF_STRIDE)                // 98304
#define OFF_KDEC  (OFF_STAGE + 2*STAGE_BYTES)   // 108672 (8B aligned)
#define DSMEM_SZ  (OFF_KDEC + KEDGE*2 + 1024)   // 114304 incl. align slack

// idesc kind::tf32: dtype=F32(bit4), atype=TF32=2, btype=TF32=2, N=256, M=128
#define IDESC_TF32_N256 ((1u<<4)|(2u<<7)|(2u<<10)|(32u<<17)|(8u<<24))

#if defined(__CUDA_ARCH_FEAT_SM103_ALL) || defined(__CUDA_ARCH_FEAT_SM100_ALL) || \
    (defined(__CUDA_ARCH_SPECIFIC__) && (__CUDA_ARCH_SPECIFIC__ >= 1000))
#define HAS_TC05 1
#else
#define HAS_TC05 0
#endif

__device__ float g_s0[BATCH*C*HW];
__device__ float g_s1[BATCH*C*HW];
__device__ __align__(16) uint32_t gA[8*NTILE_EDGE*TILE_FLOATS];  // tf32 bits, swizzled A-tiles
__device__ __align__(8) unsigned short g_kdec16[KEDGE];  // ci_rel*432+(dy+2)*36+(dx+2)
__device__ float g_asoft[8*5];

// ---------------------------------------------------------------------------
__device__ __forceinline__ uint32_t smem_u32(const void* p) {
    uint32_t a;
    asm("{ .reg .u64 t; cvta.to.shared.u64 t, %1; cvt.u32.u64 %0, t; }" : "=r"(a) : "l"(p));
    return a;
}
#define SW128(o) ((o) ^ (((o) >> 3) & 0x70))
__device__ __forceinline__ uint32_t f2tf32(float f) {
    uint32_t r;
    asm("cvt.rna.tf32.f32 %0, %1;" : "=r"(r) : "f"(f));
    return r;
}

#if HAS_TC05
__device__ __forceinline__ uint32_t elect_one() {
    uint32_t p;
    asm volatile("{ .reg .pred p; elect.sync _|p, 0xFFFFFFFF; selp.b32 %0, 1, 0, p; }" : "=r"(p));
    return p;
}
__device__ __forceinline__ uint64_t make_desc(uint32_t addr) {
    // SW128, version=1(Blackwell), SBO=64, LBO=1  (K-major, 128B rows)
    const uint64_t base = (uint64_t(2) << 61) | (uint64_t(1) << 46)
                        | (uint64_t(64) << 32) | (uint64_t(1) << 16);
    return base | ((uint64_t)(addr >> 4) & 0x3FFF);
}
__device__ __forceinline__ void mma_tf32_ss(uint32_t d, uint64_t ad, uint64_t bd,
                                            uint32_t idesc, uint32_t en) {
    asm volatile(
        "{\n\t.reg .pred p;\n\tsetp.ne.u32 p, %5, 0;\n\t"
        "tcgen05.mma.cta_group::1.kind::tf32 [%0], %1, %2, %3, {%4, %4, %4, %4}, p;\n\t}"
        :: "r"(d), "l"(ad), "l"(bd), "r"(idesc), "r"(0u), "r"(en) : "memory");
}
__device__ __forceinline__ void mbar_init(uint32_t a, uint32_t cnt) {
    asm volatile("mbarrier.init.shared.b64 [%0], %1;" :: "r"(a), "r"(cnt) : "memory");
}
__device__ __forceinline__ void mbar_inval(uint32_t a) {
    asm volatile("mbarrier.inval.shared.b64 [%0];" :: "r"(a) : "memory");
}
__device__ __forceinline__ void mbar_wait(uint32_t a, uint32_t parity) {
    asm volatile(
        "{\n\t.reg .pred P;\n"
        "W_%=:\n\t"
        "mbarrier.try_wait.parity.acquire.cta.shared::cta.b64 P, [%0], %1, 0x989680;\n\t"
        "@P bra D_%=;\n\tbra W_%=;\nD_%=:\n\t}"
        :: "r"(a), "r"(parity) : "memory");
}
__device__ __forceinline__ void mbar_expect_tx(uint32_t a, uint32_t bytes) {
    asm volatile("mbarrier.arrive.expect_tx.shared.b64 _, [%0], %1;"
                 :: "r"(a), "r"(bytes) : "memory");
}
__device__ __forceinline__ void bulk_g2s(uint32_t dst, const void* src,
                                         uint32_t bytes, uint32_t mbar) {
    asm volatile(
        "cp.async.bulk.shared::cta.global.mbarrier::complete_tx::bytes [%0], [%1], %2, [%3];"
        :: "r"(dst), "l"(src), "r"(bytes), "r"(mbar) : "memory");
}
__device__ __forceinline__ void tmem_commit(uint32_t mbar) {
    asm volatile(
        "tcgen05.commit.cta_group::1.mbarrier::arrive::one.shared::cluster.b64 [%0];"
        :: "r"(mbar) : "memory");
}
#define TC_ALLOC(dst, n)   asm volatile("tcgen05.alloc.cta_group::1.sync.aligned.shared::cta.b32 [%0], %1;" :: "r"(dst), "r"(n) : "memory")
#define TC_DEALLOC(t, n)   asm volatile("tcgen05.dealloc.cta_group::1.sync.aligned.b32 %0, %1;" :: "r"(t), "r"(n))
#define TC_RELINQ()        asm volatile("tcgen05.relinquish_alloc_permit.cta_group::1.sync.aligned;")
#define TC_FENCE_AFTER()   asm volatile("tcgen05.fence::after_thread_sync;" ::: "memory")
#define TC_FENCE_BEFORE()  asm volatile("tcgen05.fence::before_thread_sync;" ::: "memory")
#define TC_WAIT_LD()       asm volatile("tcgen05.wait::ld.sync.aligned;" ::: "memory")
#define FENCE_ASYNC()      asm volatile("fence.proxy.async.shared::cta;" ::: "memory")

#define LD_X32(r, a) \
    asm volatile("tcgen05.ld.sync.aligned.32x32b.x32.b32 " \
        "{%0,%1,%2,%3,%4,%5,%6,%7,%8,%9,%10,%11,%12,%13,%14,%15," \
        "%16,%17,%18,%19,%20,%21,%22,%23,%24,%25,%26,%27,%28,%29,%30,%31}, [%32];" \
        : "=r"((r)[0]),"=r"((r)[1]),"=r"((r)[2]),"=r"((r)[3]), \
          "=r"((r)[4]),"=r"((r)[5]),"=r"((r)[6]),"=r"((r)[7]), \
          "=r"((r)[8]),"=r"((r)[9]),"=r"((r)[10]),"=r"((r)[11]), \
          "=r"((r)[12]),"=r"((r)[13]),"=r"((r)[14]),"=r"((r)[15]), \
          "=r"((r)[16]),"=r"((r)[17]),"=r"((r)[18]),"=r"((r)[19]), \
          "=r"((r)[20]),"=r"((r)[21]),"=r"((r)[22]),"=r"((r)[23]), \
          "=r"((r)[24]),"=r"((r)[25]),"=r"((r)[26]),"=r"((r)[27]), \
          "=r"((r)[28]),"=r"((r)[29]),"=r"((r)[30]),"=r"((r)[31]) \
        : "r"(a))
#endif  // HAS_TC05

// ---------------------------------------------------------------------------
__global__ void k_softmax(const float* __restrict__ alphas) {
    int e = threadIdx.x;
    if (e < 8) {
        float m = -1e30f;
        #pragma unroll
        for (int i = 0; i < 5; i++) m = fmaxf(m, alphas[e*5+i]);
        float ex[5]; float s = 0.f;
        #pragma unroll
        for (int i = 0; i < 5; i++) { ex[i] = expf(alphas[e*5+i] - m); s += ex[i]; }
        float inv = 1.f / s;
        #pragma unroll
        for (int i = 0; i < 5; i++) g_asoft[e*5+i] = ex[i] * inv;
    }
}

// kdec16: precombined smem plane offset per k' (u16)
__global__ void k_kdec() {
    int kp = blockIdx.x * 256 + threadIdx.x;
    if (kp >= KEDGE) return;
    int ci = kp / 18, t = kp - ci*18;
    int dy, dx;
    if (t < 9) { dy = t/3 - 1; dx = t%3 - 1; }
    else { int u = t - 9; dy = (u/3)*2 - 2; dx = (u%3)*2 - 2; }
    int tile = kp >> 5;
    int ci0 = (tile*32) / 18;
    g_kdec16[kp] = (unsigned short)((ci - ci0)*PLANE + (dy+2)*36 + (dx+2));
}

// Build gA: alpha-folded conv weights + linear pool terms, swizzled tf32 tiles.
__global__ void k_combine_tiles(const float* __restrict__ w3, const float* __restrict__ wd3) {
    int idx = blockIdx.x * 256 + threadIdx.x;     // < 8*72*128*32
    int kk = idx & 31;
    int r  = idx >> 5;
    int co = r & 127;
    int et = r >> 7;                               // e*72 + tile
    int e  = et / 72, tl = et - e*72;
    int kp = tl*32 + kk;
    int ci = kp / 18, t = kp - ci*18;
    float a = (t < 9) ? g_asoft[e*5+1] : g_asoft[e*5+2];
    int tt  = (t < 9) ? t : t - 9;
    float val = a * ((t < 9 ? w3 : wd3)[((e*C + co)*C + ci)*9 + tt]);
    if (co == ci && t < 9) {
        val += g_asoft[e*5+3] * (1.f/9.f);        // avg-pool (count_include_pad)
        if (t == 4) val += g_asoft[e*5+0];        // identity (center tap)
    }
    uint32_t off = SW128((uint32_t)(co*128 + kk*4));
    *(uint32_t*)((char*)gA + (size_t)et*TILE_BYTES + off) = f2tf32(val);
}

// ---------------------------------------------------------------------------
__global__ __launch_bounds__(256) void k_pre(const float* __restrict__ in,
                                             const float* __restrict__ w,
                                             float* __restrict__ out) {
    __shared__ __align__(16) float tin[8][HW];
    __shared__ float tw[8][16];
    int b   = blockIdx.x >> 3;
    int co0 = (blockIdx.x & 7) << 4;
    int tid = threadIdx.x;
    int px0 = tid * 4;
    const float* inb = in + b*C*HW;
    float acc[16][4] = {};
    for (int cic = 0; cic < C; cic += 8) {
        __syncthreads();
        #pragma unroll
        for (int k = 0; k < 8; k++) {
            int f = tid + k*256;
            ((float4*)tin)[f] = ((const float4*)(inb + cic*HW))[f];
        }
        if (tid < 128) {
            int ci = tid >> 4, co = tid & 15;
            tw[ci][co] = w[(co0+co)*C + cic + ci];
        }
        __syncthreads();
        #pragma unroll
        for (int ci = 0; ci < 8; ci++) {
            float4 i4 = *(const float4*)&tin[ci][px0];
            float iv[4] = {i4.x, i4.y, i4.z, i4.w};
            #pragma unroll
            for (int co = 0; co < 16; co++) {
                float wv = tw[ci][co];
                #pragma unroll
                for (int j = 0; j < 4; j++) acc[co][j] += wv * iv[j];
            }
        }
    }
    float* ob = out + (b*C + co0)*HW + px0;
    #pragma unroll
    for (int co = 0; co < 16; co++)
        *(float4*)(ob + co*HW) = make_float4(acc[co][0], acc[co][1], acc[co][2], acc[co][3]);
}

// ---------------------------------------------------------------------------
// tcgen05 tf32 implicit-GEMM node kernel, N=256/CTA, register-pipelined stage.
// ---------------------------------------------------------------------------
__global__ __launch_bounds__(256) void k_node_mma(
    const float* __restrict__ h0, int h0bs,
    const float* __restrict__ h1, int h1bs,
    float* __restrict__ outR, int eA, int eB)
{
#if HAS_TC05
    extern __shared__ char dsm_raw[];
    char* dsm = (char*)(((uintptr_t)dsm_raw + 1023) & ~(uintptr_t)1023);
    uint32_t* stageU = (uint32_t*)(dsm + OFF_STAGE);          // tf32 bits
    unsigned short* kd16 = (unsigned short*)(dsm + OFF_KDEC);
    __shared__ __align__(16) uint64_t mbar[2];   // MMA-done per buffer
    __shared__ __align__(16) uint64_t abar[2];   // A-tile-arrived per buffer
    __shared__ uint32_t tmem_ptr_s;

    const int tid = threadIdx.x;
    const int wid = tid >> 5;
    const int b   = blockIdx.x >> 2;
    const int pc  = blockIdx.x & 3;

    if (wid == 0) {
        TC_ALLOC(smem_u32(&tmem_ptr_s), 256);
        TC_RELINQ();
    }
    if (tid == 0) {
        mbar_init(smem_u32(&mbar[0]), 1);
        mbar_init(smem_u32(&mbar[1]), 1);
        mbar_init(smem_u32(&abar[0]), 1);
        mbar_init(smem_u32(&abar[1]), 1);
    }
    // copy kdec table to smem (u16, via u64 chunks: 2304*2B = 576 u64)
    for (int i = tid; i < KEDGE/4; i += 256)
        ((uint64_t*)kd16)[i] = ((const uint64_t*)g_kdec16)[i];

    const uint32_t mb0 = smem_u32(&mbar[0]);
    const uint32_t mb1 = smem_u32(&mbar[1]);
    const uint32_t ab0 = smem_u32(&abar[0]);
    const uint32_t ab1 = smem_u32(&abar[1]);
    const bool leader = (wid == 0) && elect_one();

    const int px    = tid;                 // 0..255
    const int y0    = pc*8;                // block's first row
    const int tbase = (px >> 5)*36 + (px & 31);   // thread offset within plane
    const float* hA = h0 + (long long)b * h0bs;
    const float* hB = h1 + (long long)b * h1bs;

    // ---- per-thread precomputed staging indices (loop-invariant) ----
    int  sp_p[6];      // plane index or -1
    int  sgoff[6];     // gy*32+gx
    bool sval[6];      // pixel in bounds
    #pragma unroll
    for (int ii = 0; ii < 6; ii++) {
        int i = tid + ii*256;
        if (i < STAGE_FLOATS) {
            int p = i / PLANE;
            int r = i - p*PLANE;
            int row = r / 36, col = r - row*36;
            int gy = y0 + row - 2, gx = col - 2;
            sp_p[ii]  = p;
            sgoff[ii] = gy*32 + gx;
            sval[ii]  = ((unsigned)gy < 32u) && ((unsigned)gx < 32u);
        } else sp_p[ii] = -1;
    }
    float pv[6];

    auto stage_load = [&](int tt) {
        const float* img = (tt < NTILE_EDGE) ? hA : hB;
        const int te  = (tt < NTILE_EDGE) ? tt : tt - NTILE_EDGE;
        const int ci0 = (te*32) / 18;
        #pragma unroll
        for (int ii = 0; ii < 6; ii++) {
            if (sp_p[ii] >= 0) {
                int ci = ci0 + sp_p[ii]; if (ci > 127) ci = 127;
                pv[ii] = sval[ii] ? __ldg(&img[ci*HW + sgoff[ii]]) : 0.f;
            }
        }
    };
    auto stage_store = [&](int tt) {
        uint32_t* spd = stageU + (tt & 1)*STAGE_FLOATS;
        #pragma unroll
        for (int ii = 0; ii < 6; ii++)
            if (sp_p[ii] >= 0) spd[tid + ii*256] = f2tf32(pv[ii]);
    };

    int ph0 = 0, ph1 = 0;      // MMA-done phases
    int aph0 = 0, aph1 = 0;    // A-arrival phases

    stage_load(0);
    stage_store(0);
    __syncthreads();           // covers mbar init, kdec copy, stage(0)

    for (int t = 0; t < NTILES; t++) {
        const int buf = t & 1;
        const uint32_t mb = buf ? mb1 : mb0;
        const uint32_t ab = buf ? ab1 : ab0;
        if (t >= 2) {
            if (buf) { mbar_wait(mb1, ph1); ph1 ^= 1; }
            else     { mbar_wait(mb0, ph0); ph0 ^= 1; }
        }
        const int e  = (t < NTILE_EDGE) ? eA : eB;
        const int te = (t < NTILE_EDGE) ? t : t - NTILE_EDGE;
        // ---- A tile: async bulk copy of pre-swizzled tf32 tile ----
        if (leader) {
            mbar_expect_tx(ab, TILE_BYTES);
            bulk_g2s(smem_u32(dsm + buf*BUF_STRIDE),
                     (const char*)gA + (size_t)(e*NTILE_EDGE + te)*TILE_BYTES,
                     TILE_BYTES, ab);
        }
        // ---- prefetch next tile's staging loads (latency hides behind build) ----
        if (t + 1 < NTILES) stage_load(t + 1);
        // ---- B tile build from staged tf32 planes (pure LDS -> STS) ----
        {
            const uint32_t* sp = stageU + buf*STAGE_FLOATS;
            char* Bd = dsm + buf*BUF_STRIDE + TILE_BYTES;
            const unsigned short* kd = kd16 + te*32;
            #pragma unroll
            for (int g = 0; g < 8; g++) {
                ushort4 k4 = *(const ushort4*)(kd + g*4);
                uint32_t v0 = sp[k4.x + tbase];
                uint32_t v1 = sp[k4.y + tbase];
                uint32_t v2 = sp[k4.z + tbase];
                uint32_t v3 = sp[k4.w + tbase];
                uint32_t off = SW128((uint32_t)(px*128 + g*16));
                *(uint4*)(Bd + off) = make_uint4(v0, v1, v2, v3);
            }
        }
        if (t + 1 < NTILES) stage_store(t + 1);
        __syncthreads();
        if (leader) {
            FENCE_ASYNC();
            if (buf) { mbar_wait(ab1, aph1); aph1 ^= 1; }
            else     { mbar_wait(ab0, aph0); aph0 ^= 1; }
            uint64_t ad = make_desc(smem_u32(dsm + buf*BUF_STRIDE));
            uint64_t bd = make_desc(smem_u32(dsm + buf*BUF_STRIDE + TILE_BYTES));
            #pragma unroll
            for (int k = 0; k < 4; k++)
                mma_tf32_ss(tmem_ptr_s, ad + k*2, bd + k*2, IDESC_TF32_N256,
                            (t == 0 && k == 0) ? 0u : 1u);
            tmem_commit(mb);
        }
    }
    mbar_wait(mb1, ph1);
    TC_FENCE_AFTER();
    const uint32_t tmem = tmem_ptr_s;

    // ---- epilogue: 8 warps x 4 x32-loads cover 128co x 256px ----
    {
        const int lg      = wid & 3;                   // lane group (co/32)
        const uint32_t woff = ((uint32_t)lg) << 21;
        const int co      = lg*32 + (tid & 31);
        const int colbase = (wid >> 2) * 128;          // 0 or 128
        float* op = outR + (long long)b*OUT_BSTRIDE + co*HW + pc*256 + colbase;
        #pragma unroll
        for (int c = 0; c < 4; c++) {
            uint32_t r[32];
            LD_X32(r, tmem + colbase + c*32 + woff);
            TC_WAIT_LD();
            #pragma unroll
            for (int j = 0; j < 8; j++)
                ((float4*)(op + c*32))[j] = make_float4(
                    __uint_as_float(r[j*4+0]), __uint_as_float(r[j*4+1]),
                    __uint_as_float(r[j*4+2]), __uint_as_float(r[j*4+3]));
        }
        TC_FENCE_BEFORE();
    }
    __syncthreads();
    if (tid == 0) { mbar_inval(mb0); mbar_inval(mb1); mbar_inval(ab0); mbar_inval(ab1); }
    __syncthreads();
    if (wid == 0) TC_DEALLOC(tmem, 256);
#endif  // HAS_TC05
}

// ---------------------------------------------------------------------------
// max-pool term only (identity/avg folded into GEMM weights), RMW into out.
// ---------------------------------------------------------------------------
__global__ __launch_bounds__(256) void k_maxp(
    const float* __restrict__ h0, int h0bs,
    const float* __restrict__ h1, int h1bs,
    float* __restrict__ outR, int eA, int eB)
{
    __shared__ float tl[8][34*36];
    const int b  = blockIdx.x >> 5;
    const int c0 = (blockIdx.x & 31) << 2;
    const int tid = threadIdx.x;

    for (int i = tid; i < 8*34*36; i += 256) ((float*)tl)[i] = -INFINITY;
    __syncthreads();
    for (int i = tid; i < 8*HW; i += 256) {
        int e = i >> 12, ch = (i >> 10) & 3, p = i & 1023;
        int y = p >> 5, xx = p & 31;
        const float* hb = e ? (h1 + (long long)b*h1bs) : (h0 + (long long)b*h0bs);
        tl[e*4+ch][(y+1)*36 + xx + 1] = hb[(c0+ch)*HW + p];
    }
    __syncthreads();

    const float a4A = g_asoft[eA*5+4];
    const float a4B = g_asoft[eB*5+4];

    const int ch = tid >> 6;
    float* op = outR + (long long)b*OUT_BSTRIDE + (c0+ch)*HW;
    #pragma unroll 4
    for (int j = 0; j < 16; j++) {
        int p = (tid & 63) + j*64;
        int y = p >> 5, xx = p & 31;
        int base = (y+1)*36 + xx + 1;
        float acc = 0.f;
        #pragma unroll
        for (int e = 0; e < 2; e++) {
            const float* tc = tl[e*4+ch];
            float mx = -INFINITY;
            #pragma unroll
            for (int dy = -1; dy <= 1; dy++)
                #pragma unroll
                for (int dx = -1; dx <= 1; dx++)
                    mx = fmaxf(mx, tc[base + dy*36 + dx]);
            acc += (e ? a4B : a4A) * mx;
        }
        op[p] += acc;
    }
}

// ---------------------------------------------------------------------------
__global__ void k_copy_skip(const float* __restrict__ skip,
                            float* __restrict__ out,
                            float* __restrict__ out2) {
    int i = blockIdx.x * 256 + threadIdx.x;
    if (i >= (BATCH*C*HW)/4) return;
    float4 v = ((const float4*)skip)[i];
    int pe = i * 4;
    int b  = pe >> 17;
    int r  = pe & (C*HW - 1);
    *(float4*)(out + (long long)b*OUT_BSTRIDE + 4*C*HW + r) = v;
    if (out2) ((float4*)out2)[i] = v;
}

// ---------------------------------------------------------------------------
static void launch_node(const float* h0, int h0bs, const float* h1, int h1bs,
                        float* outR, int eA, int eB) {
    k_node_mma<<<BATCH*4, 256, DSMEM_SZ>>>(h0, h0bs, h1, h1bs, outR, eA, eB);
    k_maxp    <<<BATCH*32, 256>>>         (h0, h0bs, h1, h1bs, outR, eA, eB);
}

extern "C" void kernel_launch(void* const* d_in, const int* in_sizes, int n_in,
                              void* d_out, int out_size) {
    const float* input0 = (const float*)d_in[0];
    const float* input1 = (const float*)d_in[1];
    const float* skip   = (const float*)d_in[2];
    const float* w_pre0 = (const float*)d_in[3];
    const float* w_pre1 = (const float*)d_in[4];
    const float* w3     = (const float*)d_in[5];
    const float* wd3    = (const float*)d_in[6];
    const float* alphas = (const float*)d_in[7];
    float* out = (float*)d_out;

    float *s0, *s1;
    cudaGetSymbolAddress((void**)&s0, g_s0);
    cudaGetSymbolAddress((void**)&s1, g_s1);

    cudaFuncSetAttribute(k_node_mma, cudaFuncAttributeMaxDynamicSharedMemorySize, DSMEM_SZ);

    k_softmax<<<1, 8>>>(alphas);
    k_kdec<<<(KEDGE + 255)/256, 256>>>();
    k_combine_tiles<<<(8*NTILE_EDGE*TILE_FLOATS)/256, 256>>>(w3, wd3);
    k_pre<<<BATCH*8, 256>>>(input0, w_pre0, s0);
    k_pre<<<BATCH*8, 256>>>(input1, w_pre1, s1);

    launch_node(s0, REG_STRIDE, s1, REG_STRIDE,                         out + 0*C*HW, 0, 1);
    launch_node(s1, REG_STRIDE, out + 0*C*HW, OUT_BSTRIDE,              out + 1*C*HW, 2, 3);
    launch_node(out + 0*C*HW, OUT_BSTRIDE, out + 1*C*HW, OUT_BSTRIDE,   out + 2*C*HW, 4, 5);
    launch_node(out + 1*C*HW, OUT_BSTRIDE, out + 2*C*HW, OUT_BSTRIDE,   out + 3*C*HW, 6, 7);

    long long concat_elems = (long long)BATCH*OUTC*HW;
    long long skip_elems   = (long long)BATCH*C*HW;
    float* out2 = nullptr;
    if ((long long)out_size >= concat_elems + skip_elems)
        out2 = out + concat_elems;
    k_copy_skip<<<((BATCH*C*HW/4) + 255)/256, 256>>>(skip, out, out2);
}